// round 13
// baseline (speedup 1.0000x reference)
#include <cuda_runtime.h>
#include <cuda_fp16.h>
#include <math.h>
#include <cstdint>

// Problem constants
#define Bq  4
#define Sq  1024
#define Dm  1024
#define NHh 16
#define DHh 64
#define DIf 4096
#define EPS 1e-5f

// ---------------- scratch (static device globals; no allocations) ----------
__device__ float  g_ao[Bq*Sq*Dm];
__device__ float  g_x [Bq*Sq*Dm];
__device__ float  g_f [Bq*Sq*Dm];
// fp16 operands
__device__ __half g_qwh[Bq*Sq*Dm];
__device__ __half g_qrh[Bq*Sq*Dm];
__device__ __half g_kh [Bq*Sq*Dm];
__device__ __half g_vh [Bq*Sq*Dm];
__device__ __half g_rrh[Bq*Sq*Dm];
__device__ __half g_avh[Bq*Sq*Dm];
__device__ __half g_xh [Bq*Sq*Dm];
__device__ __half g_hh [Bq*Sq*DIf];
__device__ __half g_wh [Bq*Sq*Dm];
__device__ __half g_rh [Bq*Sq*Dm];
// weights TRANSPOSED ([N][K] row-major), fp16
__device__ __half g_Wqt[Dm*Dm];
__device__ __half g_Wkt[Dm*Dm];
__device__ __half g_Wvt[Dm*Dm];
__device__ __half g_Wrt[Dm*Dm];
__device__ __half g_Wot[Dm*Dm];
__device__ __half g_W1t[Dm*DIf];
__device__ __half g_W2t[DIf*Dm];

// ---------------- helpers ----------------------------------------------------
__device__ __forceinline__ void mma_f16(float* d, const uint4& a,
                                        uint32_t b0, uint32_t b1) {
    asm volatile(
        "mma.sync.aligned.m16n8k16.row.col.f32.f16.f16.f32 "
        "{%0,%1,%2,%3}, {%4,%5,%6,%7}, {%8,%9}, {%0,%1,%2,%3};"
        : "+f"(d[0]), "+f"(d[1]), "+f"(d[2]), "+f"(d[3])
        : "r"(a.x), "r"(a.y), "r"(a.z), "r"(a.w), "r"(b0), "r"(b1));
}

__device__ __forceinline__ uint4 ldsm4(unsigned addr) {
    uint4 d;
    asm volatile("ldmatrix.sync.aligned.m8n8.x4.shared.b16 {%0,%1,%2,%3}, [%4];"
                 : "=r"(d.x), "=r"(d.y), "=r"(d.z), "=r"(d.w) : "r"(addr));
    return d;
}

__device__ __forceinline__ uint4 ldsm4t(unsigned addr) {
    uint4 d;
    asm volatile("ldmatrix.sync.aligned.m8n8.x4.trans.shared.b16 {%0,%1,%2,%3}, [%4];"
                 : "=r"(d.x), "=r"(d.y), "=r"(d.z), "=r"(d.w) : "r"(addr));
    return d;
}

__device__ __forceinline__ void cp16(unsigned s, const void* g) {
    asm volatile("cp.async.cg.shared.global [%0], [%1], 16;" :: "r"(s), "l"(g));
}
#define CP_COMMIT()   asm volatile("cp.async.commit_group;")
#define CP_WAIT2()    asm volatile("cp.async.wait_group 2;")
#define CP_WAIT_ALL() asm volatile("cp.async.wait_all;" ::: "memory")

// ---------------- FP16 tensor-core GEMM (128xBN, BK=32, 4-stage) -------------
// C[M,N] = A[M,K] @ Bt[N,K]^T, both fp16 row-major (K-major).
// OUT: 0 = fp32 C, 2 = fp16 Ch (+optional dual Ch2 with bias2).
struct SelH {
    const __half* A[4]; const __half* B[4];
    float* C[4]; const float* bias[4];
    float* C2[4]; const float* bias2[4];
    __half* Ch[4]; __half* Ch2[4];
};

#define HG_A_TILE (128 * 80)

template<int BN, bool RELU, int OUT>
__global__ void __launch_bounds__(256)
hg(SelH p, int K, int ldc)
{
    constexpr int WN   = BN / 4;          // per-warp n span
    constexpr int NWT  = WN / 8;          // n8 tiles per warp
    constexpr int B_IT = (BN * 4) / 256;  // cp16 iters for B
    constexpr int B_TILE = BN * 80;
    constexpr int STG = HG_A_TILE + B_TILE;

    extern __shared__ __align__(16) char smraw[];
    const uint32_t sb = (uint32_t)__cvta_generic_to_shared(smraw);

    const int z   = blockIdx.z;
    const int tid = threadIdx.x, lane = tid & 31, wid = tid >> 5;
    const int warp_m = wid & 1, warp_n = wid >> 1;
    const long m0 = (long)blockIdx.y * 128, n0 = (long)blockIdx.x * BN;

    const __half* A  = p.A[z] + m0 * K;
    const __half* Bt = p.B[z] + n0 * K;
    const float* bias  = p.bias[z]  ? p.bias[z]  + n0 : nullptr;
    float*       C     = p.C[z]     ? p.C[z]     + m0 * ldc + n0 : nullptr;
    const float* bias2 = p.bias2[z] ? p.bias2[z] + n0 : nullptr;
    __half*      Ch    = p.Ch[z]    ? p.Ch[z]    + m0 * ldc + n0 : nullptr;
    __half*      Ch2   = p.Ch2[z]   ? p.Ch2[z]   + m0 * ldc + n0 : nullptr;

    float acc[4][NWT][4];
    #pragma unroll
    for (int i = 0; i < 4; i++)
        #pragma unroll
        for (int j = 0; j < NWT; j++)
            #pragma unroll
            for (int l = 0; l < 4; l++) acc[i][j][l] = 0.f;

    const int ntile = K >> 5;

    auto issue = [&](int c) {
        const int st = c & 3;
        const int k0 = c << 5;
        const uint32_t ab = sb + (uint32_t)st * STG;
        const uint32_t bb = ab + HG_A_TILE;
        #pragma unroll
        for (int i = 0; i < 2; i++) {
            int e = tid + i * 256;
            int row = e >> 2, sg = e & 3;
            cp16(ab + (uint32_t)(row * 80 + sg * 16),
                 &A[(long)row * K + k0 + sg * 8]);
        }
        #pragma unroll
        for (int i = 0; i < B_IT; i++) {
            int e = tid + i * 256;
            int row = e >> 2, sg = e & 3;
            cp16(bb + (uint32_t)(row * 80 + sg * 16),
                 &Bt[(long)row * K + k0 + sg * 8]);
        }
    };

    auto compute = [&](int st) {
        const uint32_t ab = sb + (uint32_t)st * STG;
        const uint32_t bb = ab + HG_A_TILE;
        const int rw = lane & 7, grp = lane >> 3;
        const uint32_t acol = (uint32_t)((grp >> 1) * 16);
        const uint32_t rsel = (uint32_t)((grp & 1) * 8 + rw);
        #pragma unroll
        for (int kb = 0; kb < 2; kb++) {
            uint4 af[4];
            #pragma unroll
            for (int mt = 0; mt < 4; mt++)
                af[mt] = ldsm4(ab + (uint32_t)(warp_m * 64 + mt * 16 + rsel) * 80
                               + kb * 32 + acol);
            uint4 bq[NWT / 2];
            #pragma unroll
            for (int nb = 0; nb < NWT / 2; nb++)
                bq[nb] = ldsm4(bb + (uint32_t)(warp_n * WN + nb * 16 + rsel) * 80
                               + kb * 32 + acol);
            #pragma unroll
            for (int mt = 0; mt < 4; mt++)
                #pragma unroll
                for (int nt = 0; nt < NWT; nt++) {
                    uint32_t b0 = (nt & 1) ? bq[nt >> 1].y : bq[nt >> 1].x;
                    uint32_t b1 = (nt & 1) ? bq[nt >> 1].w : bq[nt >> 1].z;
                    mma_f16(acc[mt][nt], af[mt], b0, b1);
                }
        }
    };

    issue(0); CP_COMMIT();
    if (ntile > 1) issue(1);
    CP_COMMIT();
    if (ntile > 2) issue(2);
    CP_COMMIT();
    for (int t = 0; t < ntile; t++) {
        CP_WAIT2();
        __syncthreads();
        if (t + 3 < ntile) issue(t + 3);
        CP_COMMIT();
        compute(t & 3);
    }

    // ---- epilogue ----
    #pragma unroll
    for (int mt = 0; mt < 4; mt++) {
        int rbase = warp_m * 64 + mt * 16 + (lane >> 2);
        #pragma unroll
        for (int nt = 0; nt < NWT; nt++) {
            int cbase = warp_n * WN + nt * 8 + (lane & 3) * 2;
            float* d = acc[mt][nt];
            float b0 = 0.f, b1 = 0.f;
            if (bias) { b0 = bias[cbase]; b1 = bias[cbase + 1]; }
            float v0 = d[0] + b0, v1 = d[1] + b1;
            float v2 = d[2] + b0, v3 = d[3] + b1;
            if (RELU) {
                v0 = fmaxf(v0, 0.f); v1 = fmaxf(v1, 0.f);
                v2 = fmaxf(v2, 0.f); v3 = fmaxf(v3, 0.f);
            }
            if (OUT == 2) {
                *(__half2*)&Ch[(long)rbase * ldc + cbase]       = __floats2half2_rn(v0, v1);
                *(__half2*)&Ch[(long)(rbase + 8) * ldc + cbase] = __floats2half2_rn(v2, v3);
                if (Ch2) {
                    float c0 = bias2[cbase], c1 = bias2[cbase + 1];
                    *(__half2*)&Ch2[(long)rbase * ldc + cbase] =
                        __floats2half2_rn(d[0] + c0, d[1] + c1);
                    *(__half2*)&Ch2[(long)(rbase + 8) * ldc + cbase] =
                        __floats2half2_rn(d[2] + c0, d[3] + c1);
                }
            } else {
                *(float2*)&C[(long)rbase * ldc + cbase]       = make_float2(v0, v1);
                *(float2*)&C[(long)(rbase + 8) * ldc + cbase] = make_float2(v2, v3);
            }
        }
    }
}

template<int BN, bool RELU, int OUT>
static void launch_hg(dim3 grid, const SelH& p, int K, int ldc)
{
    constexpr int smem = 4 * (HG_A_TILE + BN * 80);
    cudaFuncSetAttribute(hg<BN, RELU, OUT>,
                         cudaFuncAttributeMaxDynamicSharedMemorySize, smem);
    hg<BN, RELU, OUT><<<grid, 256, smem>>>(p, K, ldc);
}

// ---------------- input conversion passes ------------------------------------
__global__ void roundh_kernel(const float4* __restrict__ s0, __half* __restrict__ d0,
                              const float4* __restrict__ s1, __half* __restrict__ d1,
                              int n4) {
    const float4* s = blockIdx.y ? s1 : s0;
    __half*       d = blockIdx.y ? d1 : d0;
    for (int i = blockIdx.x * blockDim.x + threadIdx.x; i < n4;
         i += gridDim.x * blockDim.x) {
        float4 v = s[i];
        *(__half2*)&d[4 * i]     = __floats2half2_rn(v.x, v.y);
        *(__half2*)&d[4 * i + 2] = __floats2half2_rn(v.z, v.w);
    }
}

struct T7 { const float* in[7]; __half* out[7]; int K[7]; int N[7]; };

__global__ void txp_kernel(T7 t) {
    __shared__ float tb[32][33];
    const int z = blockIdx.z;
    const int K_ = t.K[z], N_ = t.N[z];
    const int n0 = blockIdx.x * 32, k0 = blockIdx.y * 32;
    if (n0 >= N_ || k0 >= K_) return;
    const int tx = threadIdx.x & 31, ty = threadIdx.x >> 5;
    #pragma unroll
    for (int i = 0; i < 32; i += 8)
        tb[ty + i][tx] = t.in[z][(long)(k0 + ty + i) * N_ + n0 + tx];
    __syncthreads();
    #pragma unroll
    for (int i = 0; i < 32; i += 8)
        t.out[z][(long)(n0 + ty + i) * K_ + k0 + tx] = __float2half_rn(tb[tx][ty + i]);
}

// ---------------- fused fp16 flash attention with rel-shift -------------------
// One CTA = 128 query rows of one (b,h). All MMAs m16n8k16 fp16, fp32 accum.
// V kept row-major; PV B-fragments via ldmatrix.trans (no scalar transpose).
// smem (bytes): K[64]x144 | V[64]x144 | rr ring[192]x144 | P/E[128]x144
#define FLH_STB  144
#define FLH_KS   0
#define FLH_VT   9216
#define FLH_RR   18432
#define FLH_PB   46080
#define FLH_TOT  64512

__global__ void __launch_bounds__(256, 2)
flash_kernel(const __half* __restrict__ qwp, const __half* __restrict__ qrp,
             const __half* __restrict__ kp,  const __half* __restrict__ rp,
             const __half* __restrict__ vp,  __half* __restrict__ avph)
{
    extern __shared__ char smh[];
    __half* Ph = (__half*)(smh + FLH_PB);
    const uint32_t base = (uint32_t)__cvta_generic_to_shared(smh);
    const uint32_t sK = base + FLH_KS;
    const uint32_t sV = base + FLH_VT;
    const uint32_t sR = base + FLH_RR;
    const uint32_t sP = base + FLH_PB;

    const int bid = blockIdx.x;
    const int it  = 7 - (bid >> 6);           // heavy blocks first
    const int bh  = bid & 63;
    const int b   = bh >> 4, h = bh & 15;
    const int i0  = it * 128;

    const int tid = threadIdx.x, lane = tid & 31, wid = tid >> 5;
    const int r0w = wid * 16;
    const int grp = lane >> 3, rw = lane & 7;
    const int r = lane >> 2, c = lane & 3;
    const uint32_t rsel = (uint32_t)((grp & 1) * 8 + rw);
    const uint32_t acol = (uint32_t)((grp >> 1) * 16);

    const long qbase  = ((long)(b * Sq + i0)) * Dm + h * 64;
    const long kvbase = ((long)b * Sq) * Dm + h * 64;

    // ---- stage Q tiles (qw -> rr area, qr -> P area); extract fragments ----
    for (int e = tid; e < 128 * 8; e += 256) {
        int row = e >> 3, sg = e & 7;
        cp16(sR + (uint32_t)(row * FLH_STB + sg * 16), &qwp[qbase + (long)row * Dm + sg * 8]);
        cp16(sP + (uint32_t)(row * FLH_STB + sg * 16), &qrp[qbase + (long)row * Dm + sg * 8]);
    }
    CP_COMMIT(); CP_WAIT_ALL(); __syncthreads();
    uint4 qwf[4], qrf[4];
    #pragma unroll
    for (int kb = 0; kb < 4; kb++) {
        uint32_t off = (uint32_t)((r0w + rsel) * FLH_STB) + kb * 32 + acol;
        qwf[kb] = ldsm4(sR + off);
        qrf[kb] = ldsm4(sP + off);
    }

    float m0v = -1e30f, m1v = -1e30f, l0v = 0.f, l1v = 0.f;
    float o_[8][4];
    #pragma unroll
    for (int i = 0; i < 8; i++)
        #pragma unroll
        for (int j = 0; j < 4; j++) o_[i][j] = 0.f;

    const int njt = (i0 >> 6) + 2;
    for (int jt = 0; jt < njt; jt++) {
        const int j0 = jt * 64;
        const int l0 = Sq - 128 + j0 - i0;    // rr window base (64-aligned, >= 0)
        __syncthreads();                       // prev-tile smem reads done

        // K + V tiles (both row-major, cp.async)
        for (int e = tid; e < 64 * 8; e += 256) {
            int row = e >> 3, sg = e & 7;
            cp16(sK + (uint32_t)(row * FLH_STB + sg * 16),
                 &kp[kvbase + (long)(j0 + row) * Dm + sg * 8]);
            cp16(sV + (uint32_t)(row * FLH_STB + sg * 16),
                 &vp[kvbase + (long)(j0 + row) * Dm + sg * 8]);
        }
        // rr ring: first tile 192 rows; later only 64 new
        {
            int rlo = (jt == 0) ? 0 : 128;
            for (int e = tid + rlo * 8; e < 192 * 8; e += 256) {
                int row = e >> 3, sg = e & 7;
                int l = l0 + row;
                int slot = (((l >> 6) % 3) << 6) + (l & 63);
                int lr = l > Sq - 1 ? Sq - 1 : l;
                cp16(sR + (uint32_t)(slot * FLH_STB + sg * 16),
                     &rp[kvbase + (long)lr * Dm + sg * 8]);
            }
        }
        CP_COMMIT();
        CP_WAIT_ALL(); __syncthreads();

        // ---- E band MMA: E[ii][d_win] -> half scatter (ii, jj=d-127+ii) ----
        {
            int dlo = 105 - r0w; if (dlo < 0) dlo = 0; dlo &= ~7;
            int dhi = (190 - r0w) & ~7;
            for (int d0 = dlo; d0 <= dhi; d0 += 16) {
                bool has2 = (d0 + 8 <= dhi);
                float e0[4] = {0.f,0.f,0.f,0.f}, e1[4] = {0.f,0.f,0.f,0.f};
                int lb = l0 + d0 + (grp & 1) * 8;          // 8-aligned in segment
                int slotb = (((lb >> 6) % 3) << 6) + (lb & 63);
                #pragma unroll
                for (int kb = 0; kb < 4; kb++) {
                    uint4 bf = ldsm4(sR + (uint32_t)((slotb + rw) * FLH_STB)
                                     + kb * 32 + acol);
                    // x = d0+0-7/k0-7, y = d0+8-15/k0-7, z = d0+0-7/k8-15, w = d0+8-15/k8-15
                    mma_f16(e0, qrf[kb], bf.x, bf.z);
                    if (has2) mma_f16(e1, qrf[kb], bf.y, bf.w);
                }
                int ii0 = r0w + r, ii1 = ii0 + 8;
                int d = d0 + 2 * c;
                int ja = d - 127 + ii0, jb = d - 127 + ii1;
                if (ja     >= 0 && ja     < 64) Ph[ii0 * 72 + ja    ] = __float2half_rn(e0[0]);
                if (ja + 1 >= 0 && ja + 1 < 64) Ph[ii0 * 72 + ja + 1] = __float2half_rn(e0[1]);
                if (jb     >= 0 && jb     < 64) Ph[ii1 * 72 + jb    ] = __float2half_rn(e0[2]);
                if (jb + 1 >= 0 && jb + 1 < 64) Ph[ii1 * 72 + jb + 1] = __float2half_rn(e0[3]);
                if (has2) {
                    int ja2 = ja + 8, jb2 = jb + 8;
                    if (ja2     >= 0 && ja2     < 64) Ph[ii0 * 72 + ja2    ] = __float2half_rn(e1[0]);
                    if (ja2 + 1 >= 0 && ja2 + 1 < 64) Ph[ii0 * 72 + ja2 + 1] = __float2half_rn(e1[1]);
                    if (jb2     >= 0 && jb2     < 64) Ph[ii1 * 72 + jb2    ] = __float2half_rn(e1[2]);
                    if (jb2 + 1 >= 0 && jb2 + 1 < 64) Ph[ii1 * 72 + jb2 + 1] = __float2half_rn(e1[3]);
                }
            }
        }
        __syncwarp();   // band written by this warp's lanes, read below

        // ---- ac MMA (fp16) ----
        float s_[8][4];
        #pragma unroll
        for (int i = 0; i < 8; i++)
            #pragma unroll
            for (int j = 0; j < 4; j++) s_[i][j] = 0.f;
        #pragma unroll
        for (int kb = 0; kb < 4; kb++) {
            #pragma unroll
            for (int nb = 0; nb < 4; nb++) {
                uint4 bq = ldsm4(sK + (uint32_t)((nb * 16 + rsel) * FLH_STB)
                                 + kb * 32 + acol);
                mma_f16(s_[2 * nb],     qwf[kb], bq.x, bq.z);
                mma_f16(s_[2 * nb + 1], qwf[kb], bq.y, bq.w);
            }
        }

        // ---- S = (ac + E)*scale, mask, online softmax ----
        const int gi0 = i0 + r0w + r, gi1 = gi0 + 8;
        float mx0 = -1e30f, mx1 = -1e30f;
        #pragma unroll
        for (int nt = 0; nt < 8; nt++) {
            int jj = nt * 8 + 2 * c, jg = j0 + jj;
            float e00 = __half2float(Ph[(r0w + r) * 72 + jj]);
            float e01 = __half2float(Ph[(r0w + r) * 72 + jj + 1]);
            float e10 = __half2float(Ph[(r0w + r + 8) * 72 + jj]);
            float e11 = __half2float(Ph[(r0w + r + 8) * 72 + jj + 1]);
            s_[nt][0] = (jg     <= gi0) ? (s_[nt][0] + e00) * 0.125f : -1e30f;
            s_[nt][1] = (jg + 1 <= gi0) ? (s_[nt][1] + e01) * 0.125f : -1e30f;
            s_[nt][2] = (jg     <= gi1) ? (s_[nt][2] + e10) * 0.125f : -1e30f;
            s_[nt][3] = (jg + 1 <= gi1) ? (s_[nt][3] + e11) * 0.125f : -1e30f;
            mx0 = fmaxf(mx0, fmaxf(s_[nt][0], s_[nt][1]));
            mx1 = fmaxf(mx1, fmaxf(s_[nt][2], s_[nt][3]));
        }
        mx0 = fmaxf(mx0, __shfl_xor_sync(0xffffffffu, mx0, 1));
        mx0 = fmaxf(mx0, __shfl_xor_sync(0xffffffffu, mx0, 2));
        mx1 = fmaxf(mx1, __shfl_xor_sync(0xffffffffu, mx1, 1));
        mx1 = fmaxf(mx1, __shfl_xor_sync(0xffffffffu, mx1, 2));
        float mn0 = fmaxf(m0v, mx0), mn1 = fmaxf(m1v, mx1);
        float a0 = __expf(m0v - mn0), a1 = __expf(m1v - mn1);
        float sum0 = 0.f, sum1 = 0.f;
        #pragma unroll
        for (int nt = 0; nt < 8; nt++) {
            int jj = nt * 8 + 2 * c;
            float p00 = __expf(s_[nt][0] - mn0), p01 = __expf(s_[nt][1] - mn0);
            float p10 = __expf(s_[nt][2] - mn1), p11 = __expf(s_[nt][3] - mn1);
            sum0 += p00 + p01; sum1 += p10 + p11;
            *(__half2*)&Ph[(r0w + r) * 72 + jj]     = __floats2half2_rn(p00, p01);
            *(__half2*)&Ph[(r0w + r + 8) * 72 + jj] = __floats2half2_rn(p10, p11);
        }
        sum0 += __shfl_xor_sync(0xffffffffu, sum0, 1);
        sum0 += __shfl_xor_sync(0xffffffffu, sum0, 2);
        sum1 += __shfl_xor_sync(0xffffffffu, sum1, 1);
        sum1 += __shfl_xor_sync(0xffffffffu, sum1, 2);
        l0v = l0v * a0 + sum0; l1v = l1v * a1 + sum1;
        m0v = mn0; m1v = mn1;
        #pragma unroll
        for (int dt = 0; dt < 8; dt++) {
            o_[dt][0] *= a0; o_[dt][1] *= a0;
            o_[dt][2] *= a1; o_[dt][3] *= a1;
        }
        __syncwarp();   // P written by this warp, read via ldmatrix below

        // ---- PV: O += P @ V (fp16); V^T fragments via ldmatrix.trans ----
        // grp0->(k0,n0) grp1->(k8,n0) grp2->(k0,n8) grp3->(k8,n8):
        //   x = b0(n-tile lo), y = b1(n-tile lo), z = b0(n-tile hi), w = b1(n-tile hi)
        #pragma unroll
        for (int kb = 0; kb < 4; kb++) {
            uint4 af = ldsm4(sP + (uint32_t)((r0w + rsel) * FLH_STB) + kb * 32 + acol);
            #pragma unroll
            for (int nb = 0; nb < 4; nb++) {
                uint4 bq = ldsm4t(sV + (uint32_t)((kb * 16 + (grp & 1) * 8 + rw) * FLH_STB)
                                  + nb * 32 + (grp >> 1) * 16);
                mma_f16(o_[2 * nb],     af, bq.x, bq.y);
                mma_f16(o_[2 * nb + 1], af, bq.z, bq.w);
            }
        }
    }

    // ---- epilogue: O / l, fp16 (feeds Wo hgemm) ----
    float i0v = 1.f / l0v, i1v = 1.f / l1v;
    long ob0 = ((long)(b * Sq + i0 + r0w + r)) * Dm + h * 64;
    long ob1 = ob0 + 8L * Dm;
    #pragma unroll
    for (int dt = 0; dt < 8; dt++) {
        int d = dt * 8 + 2 * c;
        *(__half2*)&avph[ob0 + d] = __floats2half2_rn(o_[dt][0] * i0v, o_[dt][1] * i0v);
        *(__half2*)&avph[ob1 + d] = __floats2half2_rn(o_[dt][2] * i1v, o_[dt][3] * i1v);
    }
}

// ---------------- reductions / LN --------------------------------------------
__device__ __forceinline__ float warpSum(float v) {
    #pragma unroll
    for (int o = 16; o > 0; o >>= 1) v += __shfl_xor_sync(0xffffffffu, v, o);
    return v;
}
__device__ float blockSum(float v) {
    __shared__ float red[8];
    __syncthreads();
    int lane = threadIdx.x & 31, wid = threadIdx.x >> 5;
    v = warpSum(v);
    if (lane == 0) red[wid] = v;
    __syncthreads();
    if (wid == 0) {
        float t = (lane < 8) ? red[lane] : 0.f;
        t = warpSum(t);
        if (lane == 0) red[0] = t;
    }
    __syncthreads();
    return red[0];
}

__global__ void ln_kernel(const float* __restrict__ a, const float* __restrict__ b,
                          const float* __restrict__ gam, const float* __restrict__ bet,
                          float* __restrict__ out, __half* __restrict__ out_h)
{
    const long row = blockIdx.x;
    const long base = row * Dm;
    __shared__ float sbuf[Dm];
    const int tid = threadIdx.x;

    float ls = 0.f;
    for (int j = tid; j < Dm; j += blockDim.x) {
        float x = a[base + j] + b[base + j];
        sbuf[j] = x;
        ls += x;
    }
    float mu = blockSum(ls) * (1.f / Dm);

    float lv = 0.f;
    for (int j = tid; j < Dm; j += blockDim.x) {
        float d = sbuf[j] - mu;
        lv += d * d;
    }
    float var = blockSum(lv) * (1.f / Dm);
    float inv = rsqrtf(var + EPS);

    for (int j = tid; j < Dm; j += blockDim.x) {
        float y = (sbuf[j] - mu) * inv * gam[j] + bet[j];
        out[base + j] = y;
        if (out_h) out_h[base + j] = __float2half_rn(y);
    }
}

// ---------------- launch ----------------------------------------------------
extern "C" void kernel_launch(void* const* d_in, const int* in_sizes, int n_in,
                              void* d_out, int out_size)
{
    const float* w      = (const float*)d_in[0];
    const float* r      = (const float*)d_in[1];
    const float* w_bias = (const float*)d_in[2];
    const float* r_bias = (const float*)d_in[3];
    const float* b1     = (const float*)d_in[12];
    const float* b2     = (const float*)d_in[14];
    const float* ln1g   = (const float*)d_in[9];
    const float* ln1b   = (const float*)d_in[10];
    const float* ln2g   = (const float*)d_in[15];
    const float* ln2b   = (const float*)d_in[16];
    float* out = (float*)d_out;

    float *ao, *x, *f;
    __half *qwh, *qrh, *kh, *vh, *rrh, *avh, *xh, *hh, *wh, *rh;
    __half *Wqt, *Wkt, *Wvt, *Wrt, *Wot, *W1t, *W2t;
    cudaGetSymbolAddress((void**)&ao,  g_ao);
    cudaGetSymbolAddress((void**)&x,   g_x);
    cudaGetSymbolAddress((void**)&f,   g_f);
    cudaGetSymbolAddress((void**)&qwh, g_qwh);
    cudaGetSymbolAddress((void**)&qrh, g_qrh);
    cudaGetSymbolAddress((void**)&kh,  g_kh);
    cudaGetSymbolAddress((void**)&vh,  g_vh);
    cudaGetSymbolAddress((void**)&rrh, g_rrh);
    cudaGetSymbolAddress((void**)&avh, g_avh);
    cudaGetSymbolAddress((void**)&xh,  g_xh);
    cudaGetSymbolAddress((void**)&hh,  g_hh);
    cudaGetSymbolAddress((void**)&wh,  g_wh);
    cudaGetSymbolAddress((void**)&rh,  g_rh);
    cudaGetSymbolAddress((void**)&Wqt, g_Wqt);
    cudaGetSymbolAddress((void**)&Wkt, g_Wkt);
    cudaGetSymbolAddress((void**)&Wvt, g_Wvt);
    cudaGetSymbolAddress((void**)&Wrt, g_Wrt);
    cudaGetSymbolAddress((void**)&Wot, g_Wot);
    cudaGetSymbolAddress((void**)&W1t, g_W1t);
    cudaGetSymbolAddress((void**)&W2t, g_W2t);

    const int M = Bq * Sq;

    // 0a) fp16 conversion of activations w, r
    roundh_kernel<<<dim3(512, 2), 256>>>((const float4*)w, wh,
                                         (const float4*)r, rh,
                                         Bq * Sq * Dm / 4);

    // 0b) transpose + fp16 of the 7 weights
    {
        T7 t{};
        const float* ins[7] = { (const float*)d_in[4], (const float*)d_in[5],
                                (const float*)d_in[6], (const float*)d_in[7],
                                (const float*)d_in[8], (const float*)d_in[11],
                                (const float*)d_in[13] };
        __half* outs[7] = { Wqt, Wkt, Wvt, Wrt, Wot, W1t, W2t };
        int Ks[7] = { Dm, Dm, Dm, Dm, Dm, Dm, DIf };
        int Ns[7] = { Dm, Dm, Dm, Dm, Dm, DIf, Dm };
        for (int i = 0; i < 7; i++) { t.in[i]=ins[i]; t.out[i]=outs[i]; t.K[i]=Ks[i]; t.N[i]=Ns[i]; }
        txp_kernel<<<dim3(128, 128, 7), 256>>>(t);
    }

    // 1) four projections -> fp16 outputs; q-biases fused (qw & qr dual)
    {
        SelH p{};
        p.A[0] = wh;  p.A[1] = wh;  p.A[2] = wh;  p.A[3] = rh;
        p.B[0] = Wqt; p.B[1] = Wkt; p.B[2] = Wvt; p.B[3] = Wrt;
        p.Ch[0] = qwh; p.Ch[1] = kh; p.Ch[2] = vh; p.Ch[3] = rrh;
        p.bias[0]  = w_bias;
        p.Ch2[0]   = qrh;
        p.bias2[0] = r_bias;
        launch_hg<256, false, 2>(dim3(Dm / 256, M / 128, 4), p, Dm, Dm);
    }

    // 2) fused fp16 flash attention
    cudaFuncSetAttribute(flash_kernel,
                         cudaFuncAttributeMaxDynamicSharedMemorySize, FLH_TOT);
    flash_kernel<<<512, 256, FLH_TOT>>>(qwh, qrh, kh, rrh, vh, avh);

    // 3) attn_out = av @ Wo (fp32 out)
    {
        SelH p{};
        p.A[0] = avh; p.B[0] = Wot; p.C[0] = ao;
        launch_hg<256, false, 0>(dim3(Dm / 256, M / 128, 1), p, Dm, Dm);
    }

    // 4) x = LN(w + attn_out); xh = fp16(x)
    ln_kernel<<<M, 256>>>(w, ao, ln1g, ln1b, x, xh);

    // 5) FFN: hh = fp16(relu(x @ W1 + b1)); f = hh @ W2 + b2
    {
        SelH p{};
        p.A[0] = xh; p.B[0] = W1t; p.bias[0] = b1; p.Ch[0] = hh;
        launch_hg<256, true, 2>(dim3(DIf / 256, M / 128, 1), p, Dm, DIf);
    }
    {
        SelH p{};
        p.A[0] = hh; p.B[0] = W2t; p.bias[0] = b2; p.C[0] = f;
        launch_hg<256, false, 0>(dim3(Dm / 256, M / 128, 1), p, DIf, Dm);
    }

    // 6) out = LN(x + f)
    ln_kernel<<<M, 256>>>(x, f, ln2g, ln2b, out, nullptr);
}

// round 14
// speedup vs baseline: 1.0589x; 1.0589x over previous
#include <cuda_runtime.h>
#include <cuda_fp16.h>
#include <math.h>
#include <cstdint>

// Problem constants
#define Bq  4
#define Sq  1024
#define Dm  1024
#define NHh 16
#define DHh 64
#define DIf 4096
#define EPS 1e-5f

// ---------------- scratch (static device globals; no allocations) ----------
__device__ float  g_ao[Bq*Sq*Dm];
__device__ float  g_x [Bq*Sq*Dm];
__device__ float  g_f [Bq*Sq*Dm];
// fp16 operands
__device__ __half g_qwh[Bq*Sq*Dm];
__device__ __half g_qrh[Bq*Sq*Dm];
__device__ __half g_kh [Bq*Sq*Dm];
__device__ __half g_vh [Bq*Sq*Dm];
__device__ __half g_rrh[Bq*Sq*Dm];
__device__ __half g_avh[Bq*Sq*Dm];
__device__ __half g_xh [Bq*Sq*Dm];
__device__ __half g_hh [Bq*Sq*DIf];
__device__ __half g_wh [Bq*Sq*Dm];
__device__ __half g_rh [Bq*Sq*Dm];
// weights TRANSPOSED ([N][K] row-major), fp16
__device__ __half g_Wqt[Dm*Dm];
__device__ __half g_Wkt[Dm*Dm];
__device__ __half g_Wvt[Dm*Dm];
__device__ __half g_Wrt[Dm*Dm];
__device__ __half g_Wot[Dm*Dm];
__device__ __half g_W1t[Dm*DIf];
__device__ __half g_W2t[DIf*Dm];

// ---------------- helpers ----------------------------------------------------
__device__ __forceinline__ void mma_f16(float* d, const uint4& a,
                                        uint32_t b0, uint32_t b1) {
    asm volatile(
        "mma.sync.aligned.m16n8k16.row.col.f32.f16.f16.f32 "
        "{%0,%1,%2,%3}, {%4,%5,%6,%7}, {%8,%9}, {%0,%1,%2,%3};"
        : "+f"(d[0]), "+f"(d[1]), "+f"(d[2]), "+f"(d[3])
        : "r"(a.x), "r"(a.y), "r"(a.z), "r"(a.w), "r"(b0), "r"(b1));
}

__device__ __forceinline__ uint4 ldsm4(unsigned addr) {
    uint4 d;
    asm volatile("ldmatrix.sync.aligned.m8n8.x4.shared.b16 {%0,%1,%2,%3}, [%4];"
                 : "=r"(d.x), "=r"(d.y), "=r"(d.z), "=r"(d.w) : "r"(addr));
    return d;
}

__device__ __forceinline__ uint4 ldsm4t(unsigned addr) {
    uint4 d;
    asm volatile("ldmatrix.sync.aligned.m8n8.x4.trans.shared.b16 {%0,%1,%2,%3}, [%4];"
                 : "=r"(d.x), "=r"(d.y), "=r"(d.z), "=r"(d.w) : "r"(addr));
    return d;
}

__device__ __forceinline__ void cp16(unsigned s, const void* g) {
    asm volatile("cp.async.cg.shared.global [%0], [%1], 16;" :: "r"(s), "l"(g));
}
#define CP_COMMIT()   asm volatile("cp.async.commit_group;")
#define CP_WAIT2()    asm volatile("cp.async.wait_group 2;")
#define CP_WAIT_ALL() asm volatile("cp.async.wait_all;" ::: "memory")

// ---------------- FP16 tensor-core GEMM (128x128, BK=32, 4-stage) -----------
// C[M,N] = A[M,K] @ Bt[N,K]^T, both fp16 row-major (K-major).
// OUT: 0 = fp32 C, 2 = fp16 Ch (+optional dual Ch2 with bias2).
struct SelH {
    const __half* A[4]; const __half* B[4];
    float* C[4]; const float* bias[4];
    float* C2[4]; const float* bias2[4];
    __half* Ch[4]; __half* Ch2[4];
};

#define HG_TILE  (128 * 80)
#define HG_STG   (2 * HG_TILE)
#define HG_SMEM  (4 * HG_STG)

template<bool RELU, int OUT>
__global__ void __launch_bounds__(256)
hg(SelH p, int K, int ldc)
{
    extern __shared__ __align__(16) char smraw[];
    const uint32_t sb = (uint32_t)__cvta_generic_to_shared(smraw);

    const int z   = blockIdx.z;
    const int tid = threadIdx.x, lane = tid & 31, wid = tid >> 5;
    const int warp_m = wid & 1, warp_n = wid >> 1;
    const long m0 = (long)blockIdx.y * 128, n0 = (long)blockIdx.x * 128;

    const __half* A  = p.A[z] + m0 * K;
    const __half* Bt = p.B[z] + n0 * K;
    const float* bias  = p.bias[z]  ? p.bias[z]  + n0 : nullptr;
    float*       C     = p.C[z]     ? p.C[z]     + m0 * ldc + n0 : nullptr;
    const float* bias2 = p.bias2[z] ? p.bias2[z] + n0 : nullptr;
    __half*      Ch    = p.Ch[z]    ? p.Ch[z]    + m0 * ldc + n0 : nullptr;
    __half*      Ch2   = p.Ch2[z]   ? p.Ch2[z]   + m0 * ldc + n0 : nullptr;

    float acc[4][4][4];
    #pragma unroll
    for (int i = 0; i < 4; i++)
        #pragma unroll
        for (int j = 0; j < 4; j++)
            #pragma unroll
            for (int l = 0; l < 4; l++) acc[i][j][l] = 0.f;

    const int ntile = K >> 5;

    auto issue = [&](int c) {
        const int st = c & 3;
        const int k0 = c << 5;
        const uint32_t ab = sb + (uint32_t)st * HG_STG;
        const uint32_t bb = ab + HG_TILE;
        #pragma unroll
        for (int i = 0; i < 2; i++) {
            int e = tid + i * 256;
            int row = e >> 2, sg = e & 3;
            cp16(ab + (uint32_t)(row * 80 + sg * 16),
                 &A[(long)row * K + k0 + sg * 8]);
        }
        #pragma unroll
        for (int i = 0; i < 2; i++) {
            int e = tid + i * 256;
            int row = e >> 2, sg = e & 3;
            cp16(bb + (uint32_t)(row * 80 + sg * 16),
                 &Bt[(long)row * K + k0 + sg * 8]);
        }
    };

    auto compute = [&](int st) {
        const uint32_t ab = sb + (uint32_t)st * HG_STG;
        const uint32_t bb = ab + HG_TILE;
        const int rw = lane & 7, grp = lane >> 3;
        const uint32_t acol = (uint32_t)((grp >> 1) * 16);
        const uint32_t rsel = (uint32_t)((grp & 1) * 8 + rw);
        #pragma unroll
        for (int kb = 0; kb < 2; kb++) {
            uint4 af[4];
            #pragma unroll
            for (int mt = 0; mt < 4; mt++)
                af[mt] = ldsm4(ab + (uint32_t)(warp_m * 64 + mt * 16 + rsel) * 80
                               + kb * 32 + acol);
            uint4 bq[2];
            #pragma unroll
            for (int nb = 0; nb < 2; nb++)
                bq[nb] = ldsm4(bb + (uint32_t)(warp_n * 32 + nb * 16 + rsel) * 80
                               + kb * 32 + acol);
            #pragma unroll
            for (int mt = 0; mt < 4; mt++)
                #pragma unroll
                for (int nt = 0; nt < 4; nt++) {
                    uint32_t b0 = (nt & 1) ? bq[nt >> 1].y : bq[nt >> 1].x;
                    uint32_t b1 = (nt & 1) ? bq[nt >> 1].w : bq[nt >> 1].z;
                    mma_f16(acc[mt][nt], af[mt], b0, b1);
                }
        }
    };

    issue(0); CP_COMMIT();
    if (ntile > 1) issue(1);
    CP_COMMIT();
    if (ntile > 2) issue(2);
    CP_COMMIT();
    for (int t = 0; t < ntile; t++) {
        CP_WAIT2();
        __syncthreads();
        if (t + 3 < ntile) issue(t + 3);
        CP_COMMIT();
        compute(t & 3);
    }

    // ---- epilogue ----
    #pragma unroll
    for (int mt = 0; mt < 4; mt++) {
        int rbase = warp_m * 64 + mt * 16 + (lane >> 2);
        #pragma unroll
        for (int nt = 0; nt < 4; nt++) {
            int cbase = warp_n * 32 + nt * 8 + (lane & 3) * 2;
            float* d = acc[mt][nt];
            float b0 = 0.f, b1 = 0.f;
            if (bias) { b0 = bias[cbase]; b1 = bias[cbase + 1]; }
            float v0 = d[0] + b0, v1 = d[1] + b1;
            float v2 = d[2] + b0, v3 = d[3] + b1;
            if (RELU) {
                v0 = fmaxf(v0, 0.f); v1 = fmaxf(v1, 0.f);
                v2 = fmaxf(v2, 0.f); v3 = fmaxf(v3, 0.f);
            }
            if (OUT == 2) {
                *(__half2*)&Ch[(long)rbase * ldc + cbase]       = __floats2half2_rn(v0, v1);
                *(__half2*)&Ch[(long)(rbase + 8) * ldc + cbase] = __floats2half2_rn(v2, v3);
                if (Ch2) {
                    float c0 = bias2[cbase], c1 = bias2[cbase + 1];
                    *(__half2*)&Ch2[(long)rbase * ldc + cbase] =
                        __floats2half2_rn(d[0] + c0, d[1] + c1);
                    *(__half2*)&Ch2[(long)(rbase + 8) * ldc + cbase] =
                        __floats2half2_rn(d[2] + c0, d[3] + c1);
                }
            } else {
                *(float2*)&C[(long)rbase * ldc + cbase]       = make_float2(v0, v1);
                *(float2*)&C[(long)(rbase + 8) * ldc + cbase] = make_float2(v2, v3);
            }
        }
    }
}

template<bool RELU, int OUT>
static void launch_hg(dim3 grid, const SelH& p, int K, int ldc)
{
    cudaFuncSetAttribute(hg<RELU, OUT>,
                         cudaFuncAttributeMaxDynamicSharedMemorySize, HG_SMEM);
    hg<RELU, OUT><<<grid, 256, HG_SMEM>>>(p, K, ldc);
}

// ---------------- input conversion passes ------------------------------------
__global__ void roundh_kernel(const float4* __restrict__ s0, __half* __restrict__ d0,
                              const float4* __restrict__ s1, __half* __restrict__ d1,
                              int n4) {
    const float4* s = blockIdx.y ? s1 : s0;
    __half*       d = blockIdx.y ? d1 : d0;
    for (int i = blockIdx.x * blockDim.x + threadIdx.x; i < n4;
         i += gridDim.x * blockDim.x) {
        float4 v = s[i];
        *(__half2*)&d[4 * i]     = __floats2half2_rn(v.x, v.y);
        *(__half2*)&d[4 * i + 2] = __floats2half2_rn(v.z, v.w);
    }
}

struct T7 { const float* in[7]; __half* out[7]; int K[7]; int N[7]; };

__global__ void txp_kernel(T7 t) {
    __shared__ float tb[32][33];
    const int z = blockIdx.z;
    const int K_ = t.K[z], N_ = t.N[z];
    const int n0 = blockIdx.x * 32, k0 = blockIdx.y * 32;
    if (n0 >= N_ || k0 >= K_) return;
    const int tx = threadIdx.x & 31, ty = threadIdx.x >> 5;
    #pragma unroll
    for (int i = 0; i < 32; i += 8)
        tb[ty + i][tx] = t.in[z][(long)(k0 + ty + i) * N_ + n0 + tx];
    __syncthreads();
    #pragma unroll
    for (int i = 0; i < 32; i += 8)
        t.out[z][(long)(n0 + ty + i) * K_ + k0 + tx] = __float2half_rn(tb[tx][ty + i]);
}

// ---------------- fused fp16 flash attention with rel-shift -------------------
// One CTA = 128 query rows of one (b,h). All MMAs m16n8k16 fp16, fp32 accum.
// V kept row-major; PV B-fragments via ldmatrix.trans (no scalar transpose).
// smem (bytes): K[64]x144 | V[64]x144 | rr ring[192]x144 | P/E[128]x144
#define FLH_STB  144
#define FLH_KS   0
#define FLH_VT   9216
#define FLH_RR   18432
#define FLH_PB   46080
#define FLH_TOT  64512

__global__ void __launch_bounds__(256, 2)
flash_kernel(const __half* __restrict__ qwp, const __half* __restrict__ qrp,
             const __half* __restrict__ kp,  const __half* __restrict__ rp,
             const __half* __restrict__ vp,  __half* __restrict__ avph)
{
    extern __shared__ char smh[];
    __half* Ph = (__half*)(smh + FLH_PB);
    const uint32_t base = (uint32_t)__cvta_generic_to_shared(smh);
    const uint32_t sK = base + FLH_KS;
    const uint32_t sV = base + FLH_VT;
    const uint32_t sR = base + FLH_RR;
    const uint32_t sP = base + FLH_PB;

    const int bid = blockIdx.x;
    const int it  = 7 - (bid >> 6);           // heavy blocks first
    const int bh  = bid & 63;
    const int b   = bh >> 4, h = bh & 15;
    const int i0  = it * 128;

    const int tid = threadIdx.x, lane = tid & 31, wid = tid >> 5;
    const int r0w = wid * 16;
    const int grp = lane >> 3, rw = lane & 7;
    const int r = lane >> 2, c = lane & 3;
    const uint32_t rsel = (uint32_t)((grp & 1) * 8 + rw);
    const uint32_t acol = (uint32_t)((grp >> 1) * 16);

    const long qbase  = ((long)(b * Sq + i0)) * Dm + h * 64;
    const long kvbase = ((long)b * Sq) * Dm + h * 64;

    // ---- stage Q tiles (qw -> rr area, qr -> P area); extract fragments ----
    for (int e = tid; e < 128 * 8; e += 256) {
        int row = e >> 3, sg = e & 7;
        cp16(sR + (uint32_t)(row * FLH_STB + sg * 16), &qwp[qbase + (long)row * Dm + sg * 8]);
        cp16(sP + (uint32_t)(row * FLH_STB + sg * 16), &qrp[qbase + (long)row * Dm + sg * 8]);
    }
    CP_COMMIT(); CP_WAIT_ALL(); __syncthreads();
    uint4 qwf[4], qrf[4];
    #pragma unroll
    for (int kb = 0; kb < 4; kb++) {
        uint32_t off = (uint32_t)((r0w + rsel) * FLH_STB) + kb * 32 + acol;
        qwf[kb] = ldsm4(sR + off);
        qrf[kb] = ldsm4(sP + off);
    }

    float m0v = -1e30f, m1v = -1e30f, l0v = 0.f, l1v = 0.f;
    float o_[8][4];
    #pragma unroll
    for (int i = 0; i < 8; i++)
        #pragma unroll
        for (int j = 0; j < 4; j++) o_[i][j] = 0.f;

    const int njt = (i0 >> 6) + 2;
    for (int jt = 0; jt < njt; jt++) {
        const int j0 = jt * 64;
        const int l0 = Sq - 128 + j0 - i0;    // rr window base (64-aligned, >= 0)
        __syncthreads();                       // prev-tile smem reads done

        // K + V tiles (both row-major, cp.async)
        for (int e = tid; e < 64 * 8; e += 256) {
            int row = e >> 3, sg = e & 7;
            cp16(sK + (uint32_t)(row * FLH_STB + sg * 16),
                 &kp[kvbase + (long)(j0 + row) * Dm + sg * 8]);
            cp16(sV + (uint32_t)(row * FLH_STB + sg * 16),
                 &vp[kvbase + (long)(j0 + row) * Dm + sg * 8]);
        }
        // rr ring: first tile 192 rows; later only 64 new
        {
            int rlo = (jt == 0) ? 0 : 128;
            for (int e = tid + rlo * 8; e < 192 * 8; e += 256) {
                int row = e >> 3, sg = e & 7;
                int l = l0 + row;
                int slot = (((l >> 6) % 3) << 6) + (l & 63);
                int lr = l > Sq - 1 ? Sq - 1 : l;
                cp16(sR + (uint32_t)(slot * FLH_STB + sg * 16),
                     &rp[kvbase + (long)lr * Dm + sg * 8]);
            }
        }
        CP_COMMIT();
        CP_WAIT_ALL(); __syncthreads();

        // ---- E band MMA: E[ii][d_win] -> half scatter (ii, jj=d-127+ii) ----
        {
            int dlo = 105 - r0w; if (dlo < 0) dlo = 0; dlo &= ~7;
            int dhi = (190 - r0w) & ~7;
            for (int d0 = dlo; d0 <= dhi; d0 += 16) {
                bool has2 = (d0 + 8 <= dhi);
                float e0[4] = {0.f,0.f,0.f,0.f}, e1[4] = {0.f,0.f,0.f,0.f};
                int lb = l0 + d0 + (grp & 1) * 8;          // 8-aligned in segment
                int slotb = (((lb >> 6) % 3) << 6) + (lb & 63);
                #pragma unroll
                for (int kb = 0; kb < 4; kb++) {
                    uint4 bf = ldsm4(sR + (uint32_t)((slotb + rw) * FLH_STB)
                                     + kb * 32 + acol);
                    // x = d0+0-7/k0-7, y = d0+8-15/k0-7, z = d0+0-7/k8-15, w = d0+8-15/k8-15
                    mma_f16(e0, qrf[kb], bf.x, bf.z);
                    if (has2) mma_f16(e1, qrf[kb], bf.y, bf.w);
                }
                int ii0 = r0w + r, ii1 = ii0 + 8;
                int d = d0 + 2 * c;
                int ja = d - 127 + ii0, jb = d - 127 + ii1;
                if (ja     >= 0 && ja     < 64) Ph[ii0 * 72 + ja    ] = __float2half_rn(e0[0]);
                if (ja + 1 >= 0 && ja + 1 < 64) Ph[ii0 * 72 + ja + 1] = __float2half_rn(e0[1]);
                if (jb     >= 0 && jb     < 64) Ph[ii1 * 72 + jb    ] = __float2half_rn(e0[2]);
                if (jb + 1 >= 0 && jb + 1 < 64) Ph[ii1 * 72 + jb + 1] = __float2half_rn(e0[3]);
                if (has2) {
                    int ja2 = ja + 8, jb2 = jb + 8;
                    if (ja2     >= 0 && ja2     < 64) Ph[ii0 * 72 + ja2    ] = __float2half_rn(e1[0]);
                    if (ja2 + 1 >= 0 && ja2 + 1 < 64) Ph[ii0 * 72 + ja2 + 1] = __float2half_rn(e1[1]);
                    if (jb2     >= 0 && jb2     < 64) Ph[ii1 * 72 + jb2    ] = __float2half_rn(e1[2]);
                    if (jb2 + 1 >= 0 && jb2 + 1 < 64) Ph[ii1 * 72 + jb2 + 1] = __float2half_rn(e1[3]);
                }
            }
        }
        __syncwarp();   // band written by this warp's lanes, read below

        // ---- ac MMA (fp16) ----
        float s_[8][4];
        #pragma unroll
        for (int i = 0; i < 8; i++)
            #pragma unroll
            for (int j = 0; j < 4; j++) s_[i][j] = 0.f;
        #pragma unroll
        for (int kb = 0; kb < 4; kb++) {
            #pragma unroll
            for (int nb = 0; nb < 4; nb++) {
                uint4 bq = ldsm4(sK + (uint32_t)((nb * 16 + rsel) * FLH_STB)
                                 + kb * 32 + acol);
                mma_f16(s_[2 * nb],     qwf[kb], bq.x, bq.z);
                mma_f16(s_[2 * nb + 1], qwf[kb], bq.y, bq.w);
            }
        }

        // ---- S = (ac + E)*scale, mask, online softmax ----
        const int gi0 = i0 + r0w + r, gi1 = gi0 + 8;
        float mx0 = -1e30f, mx1 = -1e30f;
        #pragma unroll
        for (int nt = 0; nt < 8; nt++) {
            int jj = nt * 8 + 2 * c, jg = j0 + jj;
            float e00 = __half2float(Ph[(r0w + r) * 72 + jj]);
            float e01 = __half2float(Ph[(r0w + r) * 72 + jj + 1]);
            float e10 = __half2float(Ph[(r0w + r + 8) * 72 + jj]);
            float e11 = __half2float(Ph[(r0w + r + 8) * 72 + jj + 1]);
            s_[nt][0] = (jg     <= gi0) ? (s_[nt][0] + e00) * 0.125f : -1e30f;
            s_[nt][1] = (jg + 1 <= gi0) ? (s_[nt][1] + e01) * 0.125f : -1e30f;
            s_[nt][2] = (jg     <= gi1) ? (s_[nt][2] + e10) * 0.125f : -1e30f;
            s_[nt][3] = (jg + 1 <= gi1) ? (s_[nt][3] + e11) * 0.125f : -1e30f;
            mx0 = fmaxf(mx0, fmaxf(s_[nt][0], s_[nt][1]));
            mx1 = fmaxf(mx1, fmaxf(s_[nt][2], s_[nt][3]));
        }
        mx0 = fmaxf(mx0, __shfl_xor_sync(0xffffffffu, mx0, 1));
        mx0 = fmaxf(mx0, __shfl_xor_sync(0xffffffffu, mx0, 2));
        mx1 = fmaxf(mx1, __shfl_xor_sync(0xffffffffu, mx1, 1));
        mx1 = fmaxf(mx1, __shfl_xor_sync(0xffffffffu, mx1, 2));
        float mn0 = fmaxf(m0v, mx0), mn1 = fmaxf(m1v, mx1);
        float a0 = __expf(m0v - mn0), a1 = __expf(m1v - mn1);
        float sum0 = 0.f, sum1 = 0.f;
        #pragma unroll
        for (int nt = 0; nt < 8; nt++) {
            int jj = nt * 8 + 2 * c;
            float p00 = __expf(s_[nt][0] - mn0), p01 = __expf(s_[nt][1] - mn0);
            float p10 = __expf(s_[nt][2] - mn1), p11 = __expf(s_[nt][3] - mn1);
            sum0 += p00 + p01; sum1 += p10 + p11;
            *(__half2*)&Ph[(r0w + r) * 72 + jj]     = __floats2half2_rn(p00, p01);
            *(__half2*)&Ph[(r0w + r + 8) * 72 + jj] = __floats2half2_rn(p10, p11);
        }
        sum0 += __shfl_xor_sync(0xffffffffu, sum0, 1);
        sum0 += __shfl_xor_sync(0xffffffffu, sum0, 2);
        sum1 += __shfl_xor_sync(0xffffffffu, sum1, 1);
        sum1 += __shfl_xor_sync(0xffffffffu, sum1, 2);
        l0v = l0v * a0 + sum0; l1v = l1v * a1 + sum1;
        m0v = mn0; m1v = mn1;
        #pragma unroll
        for (int dt = 0; dt < 8; dt++) {
            o_[dt][0] *= a0; o_[dt][1] *= a0;
            o_[dt][2] *= a1; o_[dt][3] *= a1;
        }
        __syncwarp();   // P written by this warp, read via ldmatrix below

        // ---- PV: O += P @ V (fp16); V^T fragments via ldmatrix.trans ----
        #pragma unroll
        for (int kb = 0; kb < 4; kb++) {
            uint4 af = ldsm4(sP + (uint32_t)((r0w + rsel) * FLH_STB) + kb * 32 + acol);
            #pragma unroll
            for (int nb = 0; nb < 4; nb++) {
                uint4 bq = ldsm4t(sV + (uint32_t)((kb * 16 + (grp & 1) * 8 + rw) * FLH_STB)
                                  + nb * 32 + (grp >> 1) * 16);
                mma_f16(o_[2 * nb],     af, bq.x, bq.y);
                mma_f16(o_[2 * nb + 1], af, bq.z, bq.w);
            }
        }
    }

    // ---- epilogue: O / l, fp16 (feeds Wo hgemm) ----
    float i0v = 1.f / l0v, i1v = 1.f / l1v;
    long ob0 = ((long)(b * Sq + i0 + r0w + r)) * Dm + h * 64;
    long ob1 = ob0 + 8L * Dm;
    #pragma unroll
    for (int dt = 0; dt < 8; dt++) {
        int d = dt * 8 + 2 * c;
        *(__half2*)&avph[ob0 + d] = __floats2half2_rn(o_[dt][0] * i0v, o_[dt][1] * i0v);
        *(__half2*)&avph[ob1 + d] = __floats2half2_rn(o_[dt][2] * i1v, o_[dt][3] * i1v);
    }
}

// ---------------- reductions / LN --------------------------------------------
__device__ __forceinline__ float warpSum(float v) {
    #pragma unroll
    for (int o = 16; o > 0; o >>= 1) v += __shfl_xor_sync(0xffffffffu, v, o);
    return v;
}
__device__ float blockSum(float v) {
    __shared__ float red[8];
    __syncthreads();
    int lane = threadIdx.x & 31, wid = threadIdx.x >> 5;
    v = warpSum(v);
    if (lane == 0) red[wid] = v;
    __syncthreads();
    if (wid == 0) {
        float t = (lane < 8) ? red[lane] : 0.f;
        t = warpSum(t);
        if (lane == 0) red[0] = t;
    }
    __syncthreads();
    return red[0];
}

__global__ void ln_kernel(const float* __restrict__ a, const float* __restrict__ b,
                          const float* __restrict__ gam, const float* __restrict__ bet,
                          float* __restrict__ out, __half* __restrict__ out_h)
{
    const long row = blockIdx.x;
    const long base = row * Dm;
    __shared__ float sbuf[Dm];
    const int tid = threadIdx.x;

    float ls = 0.f;
    for (int j = tid; j < Dm; j += blockDim.x) {
        float x = a[base + j] + b[base + j];
        sbuf[j] = x;
        ls += x;
    }
    float mu = blockSum(ls) * (1.f / Dm);

    float lv = 0.f;
    for (int j = tid; j < Dm; j += blockDim.x) {
        float d = sbuf[j] - mu;
        lv += d * d;
    }
    float var = blockSum(lv) * (1.f / Dm);
    float inv = rsqrtf(var + EPS);

    for (int j = tid; j < Dm; j += blockDim.x) {
        float y = (sbuf[j] - mu) * inv * gam[j] + bet[j];
        out[base + j] = y;
        if (out_h) out_h[base + j] = __float2half_rn(y);
    }
}

// ---------------- launch ----------------------------------------------------
extern "C" void kernel_launch(void* const* d_in, const int* in_sizes, int n_in,
                              void* d_out, int out_size)
{
    const float* w      = (const float*)d_in[0];
    const float* r      = (const float*)d_in[1];
    const float* w_bias = (const float*)d_in[2];
    const float* r_bias = (const float*)d_in[3];
    const float* b1     = (const float*)d_in[12];
    const float* b2     = (const float*)d_in[14];
    const float* ln1g   = (const float*)d_in[9];
    const float* ln1b   = (const float*)d_in[10];
    const float* ln2g   = (const float*)d_in[15];
    const float* ln2b   = (const float*)d_in[16];
    float* out = (float*)d_out;

    float *ao, *x, *f;
    __half *qwh, *qrh, *kh, *vh, *rrh, *avh, *xh, *hh, *wh, *rh;
    __half *Wqt, *Wkt, *Wvt, *Wrt, *Wot, *W1t, *W2t;
    cudaGetSymbolAddress((void**)&ao,  g_ao);
    cudaGetSymbolAddress((void**)&x,   g_x);
    cudaGetSymbolAddress((void**)&f,   g_f);
    cudaGetSymbolAddress((void**)&qwh, g_qwh);
    cudaGetSymbolAddress((void**)&qrh, g_qrh);
    cudaGetSymbolAddress((void**)&kh,  g_kh);
    cudaGetSymbolAddress((void**)&vh,  g_vh);
    cudaGetSymbolAddress((void**)&rrh, g_rrh);
    cudaGetSymbolAddress((void**)&avh, g_avh);
    cudaGetSymbolAddress((void**)&xh,  g_xh);
    cudaGetSymbolAddress((void**)&hh,  g_hh);
    cudaGetSymbolAddress((void**)&wh,  g_wh);
    cudaGetSymbolAddress((void**)&rh,  g_rh);
    cudaGetSymbolAddress((void**)&Wqt, g_Wqt);
    cudaGetSymbolAddress((void**)&Wkt, g_Wkt);
    cudaGetSymbolAddress((void**)&Wvt, g_Wvt);
    cudaGetSymbolAddress((void**)&Wrt, g_Wrt);
    cudaGetSymbolAddress((void**)&Wot, g_Wot);
    cudaGetSymbolAddress((void**)&W1t, g_W1t);
    cudaGetSymbolAddress((void**)&W2t, g_W2t);

    const int M = Bq * Sq;

    // 0a) fp16 conversion of activations w, r
    roundh_kernel<<<dim3(512, 2), 256>>>((const float4*)w, wh,
                                         (const float4*)r, rh,
                                         Bq * Sq * Dm / 4);

    // 0b) transpose + fp16 of the 7 weights
    {
        T7 t{};
        const float* ins[7] = { (const float*)d_in[4], (const float*)d_in[5],
                                (const float*)d_in[6], (const float*)d_in[7],
                                (const float*)d_in[8], (const float*)d_in[11],
                                (const float*)d_in[13] };
        __half* outs[7] = { Wqt, Wkt, Wvt, Wrt, Wot, W1t, W2t };
        int Ks[7] = { Dm, Dm, Dm, Dm, Dm, Dm, DIf };
        int Ns[7] = { Dm, Dm, Dm, Dm, Dm, DIf, Dm };
        for (int i = 0; i < 7; i++) { t.in[i]=ins[i]; t.out[i]=outs[i]; t.K[i]=Ks[i]; t.N[i]=Ns[i]; }
        txp_kernel<<<dim3(128, 128, 7), 256>>>(t);
    }

    // 1) four projections -> fp16 outputs; q-biases fused (qw & qr dual)
    {
        SelH p{};
        p.A[0] = wh;  p.A[1] = wh;  p.A[2] = wh;  p.A[3] = rh;
        p.B[0] = Wqt; p.B[1] = Wkt; p.B[2] = Wvt; p.B[3] = Wrt;
        p.Ch[0] = qwh; p.Ch[1] = kh; p.Ch[2] = vh; p.Ch[3] = rrh;
        p.bias[0]  = w_bias;
        p.Ch2[0]   = qrh;
        p.bias2[0] = r_bias;
        launch_hg<false, 2>(dim3(Dm / 128, M / 128, 4), p, Dm, Dm);
    }

    // 2) fused fp16 flash attention
    cudaFuncSetAttribute(flash_kernel,
                         cudaFuncAttributeMaxDynamicSharedMemorySize, FLH_TOT);
    flash_kernel<<<512, 256, FLH_TOT>>>(qwh, qrh, kh, rrh, vh, avh);

    // 3) attn_out = av @ Wo (fp32 out)
    {
        SelH p{};
        p.A[0] = avh; p.B[0] = Wot; p.C[0] = ao;
        launch_hg<false, 0>(dim3(Dm / 128, M / 128, 1), p, Dm, Dm);
    }

    // 4) x = LN(w + attn_out); xh = fp16(x)
    ln_kernel<<<M, 256>>>(w, ao, ln1g, ln1b, x, xh);

    // 5) FFN: hh = fp16(relu(x @ W1 + b1)); f = hh @ W2 + b2
    {
        SelH p{};
        p.A[0] = xh; p.B[0] = W1t; p.bias[0] = b1; p.Ch[0] = hh;
        launch_hg<true, 2>(dim3(DIf / 128, M / 128, 1), p, Dm, DIf);
    }
    {
        SelH p{};
        p.A[0] = hh; p.B[0] = W2t; p.bias[0] = b2; p.C[0] = f;
        launch_hg<false, 0>(dim3(Dm / 128, M / 128, 1), p, DIf, Dm);
    }

    // 6) out = LN(x + f)
    ln_kernel<<<M, 256>>>(x, f, ln2g, ln2b, out, nullptr);
}

// round 15
// speedup vs baseline: 1.1513x; 1.0872x over previous
#include <cuda_runtime.h>
#include <cuda_fp16.h>
#include <math.h>
#include <cstdint>

// Problem constants
#define Bq  4
#define Sq  1024
#define Dm  1024
#define NHh 16
#define DHh 64
#define DIf 4096
#define EPS 1e-5f

// ---------------- scratch (static device globals; no allocations) ----------
__device__ float  g_ao[Bq*Sq*Dm];
__device__ float  g_x [Bq*Sq*Dm];
__device__ float  g_f [Bq*Sq*Dm];
// fp16 operands
__device__ __half g_qwh[Bq*Sq*Dm];
__device__ __half g_qrh[Bq*Sq*Dm];
__device__ __half g_kh [Bq*Sq*Dm];
__device__ __half g_vh [Bq*Sq*Dm];
__device__ __half g_rrh[Bq*Sq*Dm];
__device__ __half g_avh[Bq*Sq*Dm];
__device__ __half g_xh [Bq*Sq*Dm];
__device__ __half g_hh [Bq*Sq*DIf];
__device__ __half g_wh [Bq*Sq*Dm];
__device__ __half g_rh [Bq*Sq*Dm];
// weights TRANSPOSED ([N][K] row-major), fp16
__device__ __half g_Wqt[Dm*Dm];
__device__ __half g_Wkt[Dm*Dm];
__device__ __half g_Wvt[Dm*Dm];
__device__ __half g_Wrt[Dm*Dm];
__device__ __half g_Wot[Dm*Dm];
__device__ __half g_W1t[Dm*DIf];
__device__ __half g_W2t[DIf*Dm];

// ---------------- helpers ----------------------------------------------------
__device__ __forceinline__ void mma_f16(float* d, const uint4& a,
                                        uint32_t b0, uint32_t b1) {
    asm volatile(
        "mma.sync.aligned.m16n8k16.row.col.f32.f16.f16.f32 "
        "{%0,%1,%2,%3}, {%4,%5,%6,%7}, {%8,%9}, {%0,%1,%2,%3};"
        : "+f"(d[0]), "+f"(d[1]), "+f"(d[2]), "+f"(d[3])
        : "r"(a.x), "r"(a.y), "r"(a.z), "r"(a.w), "r"(b0), "r"(b1));
}

__device__ __forceinline__ uint4 ldsm4(unsigned addr) {
    uint4 d;
    asm volatile("ldmatrix.sync.aligned.m8n8.x4.shared.b16 {%0,%1,%2,%3}, [%4];"
                 : "=r"(d.x), "=r"(d.y), "=r"(d.z), "=r"(d.w) : "r"(addr));
    return d;
}

__device__ __forceinline__ uint4 ldsm4t(unsigned addr) {
    uint4 d;
    asm volatile("ldmatrix.sync.aligned.m8n8.x4.trans.shared.b16 {%0,%1,%2,%3}, [%4];"
                 : "=r"(d.x), "=r"(d.y), "=r"(d.z), "=r"(d.w) : "r"(addr));
    return d;
}

__device__ __forceinline__ void cp16(unsigned s, const void* g) {
    asm volatile("cp.async.cg.shared.global [%0], [%1], 16;" :: "r"(s), "l"(g));
}
#define CP_COMMIT()   asm volatile("cp.async.commit_group;")
#define CP_WAIT_ALL() asm volatile("cp.async.wait_all;" ::: "memory")

// ---------------- FP16 tensor-core GEMM (128x128, 2 BK=32 chunks/barrier) ---
// C[M,N] = A[M,K] @ Bt[N,K]^T, both fp16 row-major (K-major).
// OUT: 0 = fp32 C, 2 = fp16 Ch (+optional dual Ch2 with bias2).
struct SelH {
    const __half* A[4]; const __half* B[4];
    float* C[4]; const float* bias[4];
    float* C2[4]; const float* bias2[4];
    __half* Ch[4]; __half* Ch2[4];
};

#define HG_TILE  (128 * 80)
#define HG_STG   (2 * HG_TILE)
#define HG_SMEM  (4 * HG_STG)

template<bool RELU, int OUT>
__global__ void __launch_bounds__(256)
hg(SelH p, int K, int ldc)
{
    extern __shared__ __align__(16) char smraw[];
    const uint32_t sb = (uint32_t)__cvta_generic_to_shared(smraw);

    const int z   = blockIdx.z;
    const int tid = threadIdx.x, lane = tid & 31, wid = tid >> 5;
    const int warp_m = wid & 1, warp_n = wid >> 1;
    const long m0 = (long)blockIdx.y * 128, n0 = (long)blockIdx.x * 128;

    const __half* A  = p.A[z] + m0 * K;
    const __half* Bt = p.B[z] + n0 * K;
    const float* bias  = p.bias[z]  ? p.bias[z]  + n0 : nullptr;
    float*       C     = p.C[z]     ? p.C[z]     + m0 * ldc + n0 : nullptr;
    const float* bias2 = p.bias2[z] ? p.bias2[z] + n0 : nullptr;
    __half*      Ch    = p.Ch[z]    ? p.Ch[z]    + m0 * ldc + n0 : nullptr;
    __half*      Ch2   = p.Ch2[z]   ? p.Ch2[z]   + m0 * ldc + n0 : nullptr;

    float acc[4][4][4];
    #pragma unroll
    for (int i = 0; i < 4; i++)
        #pragma unroll
        for (int j = 0; j < 4; j++)
            #pragma unroll
            for (int l = 0; l < 4; l++) acc[i][j][l] = 0.f;

    const int ntile = K >> 5;

    auto issue = [&](int c) {
        const int st = c & 3;
        const int k0 = c << 5;
        const uint32_t ab = sb + (uint32_t)st * HG_STG;
        const uint32_t bb = ab + HG_TILE;
        #pragma unroll
        for (int i = 0; i < 2; i++) {
            int e = tid + i * 256;
            int row = e >> 2, sg = e & 3;
            cp16(ab + (uint32_t)(row * 80 + sg * 16),
                 &A[(long)row * K + k0 + sg * 8]);
        }
        #pragma unroll
        for (int i = 0; i < 2; i++) {
            int e = tid + i * 256;
            int row = e >> 2, sg = e & 3;
            cp16(bb + (uint32_t)(row * 80 + sg * 16),
                 &Bt[(long)row * K + k0 + sg * 8]);
        }
    };

    auto compute = [&](int st) {
        const uint32_t ab = sb + (uint32_t)st * HG_STG;
        const uint32_t bb = ab + HG_TILE;
        const int rw = lane & 7, grp = lane >> 3;
        const uint32_t acol = (uint32_t)((grp >> 1) * 16);
        const uint32_t rsel = (uint32_t)((grp & 1) * 8 + rw);
        #pragma unroll
        for (int kb = 0; kb < 2; kb++) {
            uint4 af[4];
            #pragma unroll
            for (int mt = 0; mt < 4; mt++)
                af[mt] = ldsm4(ab + (uint32_t)(warp_m * 64 + mt * 16 + rsel) * 80
                               + kb * 32 + acol);
            uint4 bq[2];
            #pragma unroll
            for (int nb = 0; nb < 2; nb++)
                bq[nb] = ldsm4(bb + (uint32_t)(warp_n * 32 + nb * 16 + rsel) * 80
                               + kb * 32 + acol);
            #pragma unroll
            for (int mt = 0; mt < 4; mt++)
                #pragma unroll
                for (int nt = 0; nt < 4; nt++) {
                    uint32_t b0 = (nt & 1) ? bq[nt >> 1].y : bq[nt >> 1].x;
                    uint32_t b1 = (nt & 1) ? bq[nt >> 1].w : bq[nt >> 1].z;
                    mma_f16(acc[mt][nt], af[mt], b0, b1);
                }
        }
    };

    // 2 chunks per barrier: iteration t waits chunks t,t+1; issues t+2,t+3
    // between the two computes (consumed buffers were freed 2 iterations ago,
    // guarded by this iteration's barrier).
    issue(0); CP_COMMIT();
    if (ntile > 1) issue(1);
    CP_COMMIT();
    for (int t = 0; t < ntile; t += 2) {
        CP_WAIT_ALL();
        __syncthreads();
        if (t + 2 < ntile) issue(t + 2);
        CP_COMMIT();
        compute(t & 3);
        if (t + 3 < ntile) issue(t + 3);
        CP_COMMIT();
        if (t + 1 < ntile) compute((t + 1) & 3);
    }

    // ---- epilogue ----
    #pragma unroll
    for (int mt = 0; mt < 4; mt++) {
        int rbase = warp_m * 64 + mt * 16 + (lane >> 2);
        #pragma unroll
        for (int nt = 0; nt < 4; nt++) {
            int cbase = warp_n * 32 + nt * 8 + (lane & 3) * 2;
            float* d = acc[mt][nt];
            float b0 = 0.f, b1 = 0.f;
            if (bias) { b0 = bias[cbase]; b1 = bias[cbase + 1]; }
            float v0 = d[0] + b0, v1 = d[1] + b1;
            float v2 = d[2] + b0, v3 = d[3] + b1;
            if (RELU) {
                v0 = fmaxf(v0, 0.f); v1 = fmaxf(v1, 0.f);
                v2 = fmaxf(v2, 0.f); v3 = fmaxf(v3, 0.f);
            }
            if (OUT == 2) {
                *(__half2*)&Ch[(long)rbase * ldc + cbase]       = __floats2half2_rn(v0, v1);
                *(__half2*)&Ch[(long)(rbase + 8) * ldc + cbase] = __floats2half2_rn(v2, v3);
                if (Ch2) {
                    float c0 = bias2[cbase], c1 = bias2[cbase + 1];
                    *(__half2*)&Ch2[(long)rbase * ldc + cbase] =
                        __floats2half2_rn(d[0] + c0, d[1] + c1);
                    *(__half2*)&Ch2[(long)(rbase + 8) * ldc + cbase] =
                        __floats2half2_rn(d[2] + c0, d[3] + c1);
                }
            } else {
                *(float2*)&C[(long)rbase * ldc + cbase]       = make_float2(v0, v1);
                *(float2*)&C[(long)(rbase + 8) * ldc + cbase] = make_float2(v2, v3);
            }
        }
    }
}

template<bool RELU, int OUT>
static void launch_hg(dim3 grid, const SelH& p, int K, int ldc)
{
    cudaFuncSetAttribute(hg<RELU, OUT>,
                         cudaFuncAttributeMaxDynamicSharedMemorySize, HG_SMEM);
    hg<RELU, OUT><<<grid, 256, HG_SMEM>>>(p, K, ldc);
}

// ---------------- input conversion passes ------------------------------------
__global__ void roundh_kernel(const float4* __restrict__ s0, __half* __restrict__ d0,
                              const float4* __restrict__ s1, __half* __restrict__ d1,
                              int n4) {
    const float4* s = blockIdx.y ? s1 : s0;
    __half*       d = blockIdx.y ? d1 : d0;
    for (int i = blockIdx.x * blockDim.x + threadIdx.x; i < n4;
         i += gridDim.x * blockDim.x) {
        float4 v = s[i];
        *(__half2*)&d[4 * i]     = __floats2half2_rn(v.x, v.y);
        *(__half2*)&d[4 * i + 2] = __floats2half2_rn(v.z, v.w);
    }
}

struct T7 { const float* in[7]; __half* out[7]; int K[7]; int N[7]; };

__global__ void txp_kernel(T7 t) {
    __shared__ float tb[32][33];
    const int z = blockIdx.z;
    const int K_ = t.K[z], N_ = t.N[z];
    const int n0 = blockIdx.x * 32, k0 = blockIdx.y * 32;
    if (n0 >= N_ || k0 >= K_) return;
    const int tx = threadIdx.x & 31, ty = threadIdx.x >> 5;
    #pragma unroll
    for (int i = 0; i < 32; i += 8)
        tb[ty + i][tx] = t.in[z][(long)(k0 + ty + i) * N_ + n0 + tx];
    __syncthreads();
    #pragma unroll
    for (int i = 0; i < 32; i += 8)
        t.out[z][(long)(n0 + ty + i) * K_ + k0 + tx] = __float2half_rn(tb[tx][ty + i]);
}

// ---------------- fused fp16 flash attention with rel-shift -------------------
// One CTA = 128 query rows of one (b,h). All MMAs m16n8k16 fp16, fp32 accum.
// V row-major; PV B-fragments via ldmatrix.trans. rr ring = 4 x 64-row
// segments so slot = l & 255 (no modulo).
// smem (bytes): K[64]x144 | V[64]x144 | rr ring[256]x144 | P/E[128]x144
#define FLH_STB  144
#define FLH_KS   0
#define FLH_VT   9216
#define FLH_RR   18432
#define FLH_PB   55296
#define FLH_TOT  73728

__global__ void __launch_bounds__(256, 2)
flash_kernel(const __half* __restrict__ qwp, const __half* __restrict__ qrp,
             const __half* __restrict__ kp,  const __half* __restrict__ rp,
             const __half* __restrict__ vp,  __half* __restrict__ avph)
{
    extern __shared__ char smh[];
    __half* Ph = (__half*)(smh + FLH_PB);
    const uint32_t base = (uint32_t)__cvta_generic_to_shared(smh);
    const uint32_t sK = base + FLH_KS;
    const uint32_t sV = base + FLH_VT;
    const uint32_t sR = base + FLH_RR;
    const uint32_t sP = base + FLH_PB;

    const int bid = blockIdx.x;
    const int it  = 7 - (bid >> 6);           // heavy blocks first
    const int bh  = bid & 63;
    const int b   = bh >> 4, h = bh & 15;
    const int i0  = it * 128;

    const int tid = threadIdx.x, lane = tid & 31, wid = tid >> 5;
    const int r0w = wid * 16;
    const int grp = lane >> 3, rw = lane & 7;
    const int r = lane >> 2, c = lane & 3;
    const uint32_t rsel = (uint32_t)((grp & 1) * 8 + rw);
    const uint32_t acol = (uint32_t)((grp >> 1) * 16);

    const long qbase  = ((long)(b * Sq + i0)) * Dm + h * 64;
    const long kvbase = ((long)b * Sq) * Dm + h * 64;

    // ---- stage Q tiles (qw -> rr area, qr -> P area); extract fragments ----
    for (int e = tid; e < 128 * 8; e += 256) {
        int row = e >> 3, sg = e & 7;
        cp16(sR + (uint32_t)(row * FLH_STB + sg * 16), &qwp[qbase + (long)row * Dm + sg * 8]);
        cp16(sP + (uint32_t)(row * FLH_STB + sg * 16), &qrp[qbase + (long)row * Dm + sg * 8]);
    }
    CP_COMMIT(); CP_WAIT_ALL(); __syncthreads();
    uint4 qwf[4], qrf[4];
    #pragma unroll
    for (int kb = 0; kb < 4; kb++) {
        uint32_t off = (uint32_t)((r0w + rsel) * FLH_STB) + kb * 32 + acol;
        qwf[kb] = ldsm4(sR + off);
        qrf[kb] = ldsm4(sP + off);
    }

    float m0v = -1e30f, m1v = -1e30f, l0v = 0.f, l1v = 0.f;
    float o_[8][4];
    #pragma unroll
    for (int i = 0; i < 8; i++)
        #pragma unroll
        for (int j = 0; j < 4; j++) o_[i][j] = 0.f;

    const int njt = (i0 >> 6) + 2;
    for (int jt = 0; jt < njt; jt++) {
        const int j0 = jt * 64;
        const int l0 = Sq - 128 + j0 - i0;    // rr window base (64-aligned, >= 0)
        __syncthreads();                       // prev-tile smem reads done

        // K + V tiles (both row-major, cp.async)
        for (int e = tid; e < 64 * 8; e += 256) {
            int row = e >> 3, sg = e & 7;
            cp16(sK + (uint32_t)(row * FLH_STB + sg * 16),
                 &kp[kvbase + (long)(j0 + row) * Dm + sg * 8]);
            cp16(sV + (uint32_t)(row * FLH_STB + sg * 16),
                 &vp[kvbase + (long)(j0 + row) * Dm + sg * 8]);
        }
        // rr ring: first tile 192 rows; later only 64 new; slot = l & 255
        {
            int rlo = (jt == 0) ? 0 : 128;
            for (int e = tid + rlo * 8; e < 192 * 8; e += 256) {
                int row = e >> 3, sg = e & 7;
                int l = l0 + row;
                int slot = l & 255;
                int lr = l > Sq - 1 ? Sq - 1 : l;
                cp16(sR + (uint32_t)(slot * FLH_STB + sg * 16),
                     &rp[kvbase + (long)lr * Dm + sg * 8]);
            }
        }
        CP_COMMIT();
        CP_WAIT_ALL(); __syncthreads();

        // ---- E band MMA: E[ii][d_win] -> half scatter (ii, jj=d-127+ii) ----
        {
            int dlo = 105 - r0w; if (dlo < 0) dlo = 0; dlo &= ~7;
            int dhi = (190 - r0w) & ~7;
            for (int d0 = dlo; d0 <= dhi; d0 += 16) {
                bool has2 = (d0 + 8 <= dhi);
                float e0[4] = {0.f,0.f,0.f,0.f}, e1[4] = {0.f,0.f,0.f,0.f};
                int lb = l0 + d0 + (grp & 1) * 8;          // 8-aligned in segment
                int slotb = lb & 255;
                #pragma unroll
                for (int kb = 0; kb < 4; kb++) {
                    uint4 bf = ldsm4(sR + (uint32_t)((slotb + rw) * FLH_STB)
                                     + kb * 32 + acol);
                    // x = d0+0-7/k0-7, y = d0+8-15/k0-7, z = d0+0-7/k8-15, w = d0+8-15/k8-15
                    mma_f16(e0, qrf[kb], bf.x, bf.z);
                    if (has2) mma_f16(e1, qrf[kb], bf.y, bf.w);
                }
                int ii0 = r0w + r, ii1 = ii0 + 8;
                int d = d0 + 2 * c;
                int ja = d - 127 + ii0, jb = d - 127 + ii1;
                if (ja     >= 0 && ja     < 64) Ph[ii0 * 72 + ja    ] = __float2half_rn(e0[0]);
                if (ja + 1 >= 0 && ja + 1 < 64) Ph[ii0 * 72 + ja + 1] = __float2half_rn(e0[1]);
                if (jb     >= 0 && jb     < 64) Ph[ii1 * 72 + jb    ] = __float2half_rn(e0[2]);
                if (jb + 1 >= 0 && jb + 1 < 64) Ph[ii1 * 72 + jb + 1] = __float2half_rn(e0[3]);
                if (has2) {
                    int ja2 = ja + 8, jb2 = jb + 8;
                    if (ja2     >= 0 && ja2     < 64) Ph[ii0 * 72 + ja2    ] = __float2half_rn(e1[0]);
                    if (ja2 + 1 >= 0 && ja2 + 1 < 64) Ph[ii0 * 72 + ja2 + 1] = __float2half_rn(e1[1]);
                    if (jb2     >= 0 && jb2     < 64) Ph[ii1 * 72 + jb2    ] = __float2half_rn(e1[2]);
                    if (jb2 + 1 >= 0 && jb2 + 1 < 64) Ph[ii1 * 72 + jb2 + 1] = __float2half_rn(e1[3]);
                }
            }
        }
        __syncwarp();   // band written by this warp's lanes, read below

        // ---- ac MMA (fp16) ----
        float s_[8][4];
        #pragma unroll
        for (int i = 0; i < 8; i++)
            #pragma unroll
            for (int j = 0; j < 4; j++) s_[i][j] = 0.f;
        #pragma unroll
        for (int kb = 0; kb < 4; kb++) {
            #pragma unroll
            for (int nb = 0; nb < 4; nb++) {
                uint4 bq = ldsm4(sK + (uint32_t)((nb * 16 + rsel) * FLH_STB)
                                 + kb * 32 + acol);
                mma_f16(s_[2 * nb],     qwf[kb], bq.x, bq.z);
                mma_f16(s_[2 * nb + 1], qwf[kb], bq.y, bq.w);
            }
        }

        // ---- S = (ac + E)*scale, mask, online softmax ----
        const int gi0 = i0 + r0w + r, gi1 = gi0 + 8;
        float mx0 = -1e30f, mx1 = -1e30f;
        #pragma unroll
        for (int nt = 0; nt < 8; nt++) {
            int jj = nt * 8 + 2 * c, jg = j0 + jj;
            float e00 = __half2float(Ph[(r0w + r) * 72 + jj]);
            float e01 = __half2float(Ph[(r0w + r) * 72 + jj + 1]);
            float e10 = __half2float(Ph[(r0w + r + 8) * 72 + jj]);
            float e11 = __half2float(Ph[(r0w + r + 8) * 72 + jj + 1]);
            s_[nt][0] = (jg     <= gi0) ? (s_[nt][0] + e00) * 0.125f : -1e30f;
            s_[nt][1] = (jg + 1 <= gi0) ? (s_[nt][1] + e01) * 0.125f : -1e30f;
            s_[nt][2] = (jg     <= gi1) ? (s_[nt][2] + e10) * 0.125f : -1e30f;
            s_[nt][3] = (jg + 1 <= gi1) ? (s_[nt][3] + e11) * 0.125f : -1e30f;
            mx0 = fmaxf(mx0, fmaxf(s_[nt][0], s_[nt][1]));
            mx1 = fmaxf(mx1, fmaxf(s_[nt][2], s_[nt][3]));
        }
        mx0 = fmaxf(mx0, __shfl_xor_sync(0xffffffffu, mx0, 1));
        mx0 = fmaxf(mx0, __shfl_xor_sync(0xffffffffu, mx0, 2));
        mx1 = fmaxf(mx1, __shfl_xor_sync(0xffffffffu, mx1, 1));
        mx1 = fmaxf(mx1, __shfl_xor_sync(0xffffffffu, mx1, 2));
        float mn0 = fmaxf(m0v, mx0), mn1 = fmaxf(m1v, mx1);
        float a0 = __expf(m0v - mn0), a1 = __expf(m1v - mn1);
        float sum0 = 0.f, sum1 = 0.f;
        #pragma unroll
        for (int nt = 0; nt < 8; nt++) {
            int jj = nt * 8 + 2 * c;
            float p00 = __expf(s_[nt][0] - mn0), p01 = __expf(s_[nt][1] - mn0);
            float p10 = __expf(s_[nt][2] - mn1), p11 = __expf(s_[nt][3] - mn1);
            sum0 += p00 + p01; sum1 += p10 + p11;
            *(__half2*)&Ph[(r0w + r) * 72 + jj]     = __floats2half2_rn(p00, p01);
            *(__half2*)&Ph[(r0w + r + 8) * 72 + jj] = __floats2half2_rn(p10, p11);
        }
        sum0 += __shfl_xor_sync(0xffffffffu, sum0, 1);
        sum0 += __shfl_xor_sync(0xffffffffu, sum0, 2);
        sum1 += __shfl_xor_sync(0xffffffffu, sum1, 1);
        sum1 += __shfl_xor_sync(0xffffffffu, sum1, 2);
        l0v = l0v * a0 + sum0; l1v = l1v * a1 + sum1;
        m0v = mn0; m1v = mn1;
        #pragma unroll
        for (int dt = 0; dt < 8; dt++) {
            o_[dt][0] *= a0; o_[dt][1] *= a0;
            o_[dt][2] *= a1; o_[dt][3] *= a1;
        }
        __syncwarp();   // P written by this warp, read via ldmatrix below

        // ---- PV: O += P @ V (fp16); V^T fragments via ldmatrix.trans ----
        #pragma unroll
        for (int kb = 0; kb < 4; kb++) {
            uint4 af = ldsm4(sP + (uint32_t)((r0w + rsel) * FLH_STB) + kb * 32 + acol);
            #pragma unroll
            for (int nb = 0; nb < 4; nb++) {
                uint4 bq = ldsm4t(sV + (uint32_t)((kb * 16 + (grp & 1) * 8 + rw) * FLH_STB)
                                  + nb * 32 + (grp >> 1) * 16);
                mma_f16(o_[2 * nb],     af, bq.x, bq.y);
                mma_f16(o_[2 * nb + 1], af, bq.z, bq.w);
            }
        }
    }

    // ---- epilogue: O / l, fp16 (feeds Wo hgemm) ----
    float i0v = 1.f / l0v, i1v = 1.f / l1v;
    long ob0 = ((long)(b * Sq + i0 + r0w + r)) * Dm + h * 64;
    long ob1 = ob0 + 8L * Dm;
    #pragma unroll
    for (int dt = 0; dt < 8; dt++) {
        int d = dt * 8 + 2 * c;
        *(__half2*)&avph[ob0 + d] = __floats2half2_rn(o_[dt][0] * i0v, o_[dt][1] * i0v);
        *(__half2*)&avph[ob1 + d] = __floats2half2_rn(o_[dt][2] * i1v, o_[dt][3] * i1v);
    }
}

// ---------------- reductions / LN --------------------------------------------
__device__ __forceinline__ float warpSum(float v) {
    #pragma unroll
    for (int o = 16; o > 0; o >>= 1) v += __shfl_xor_sync(0xffffffffu, v, o);
    return v;
}
__device__ float blockSum(float v) {
    __shared__ float red[8];
    __syncthreads();
    int lane = threadIdx.x & 31, wid = threadIdx.x >> 5;
    v = warpSum(v);
    if (lane == 0) red[wid] = v;
    __syncthreads();
    if (wid == 0) {
        float t = (lane < 8) ? red[lane] : 0.f;
        t = warpSum(t);
        if (lane == 0) red[0] = t;
    }
    __syncthreads();
    return red[0];
}

__global__ void ln_kernel(const float* __restrict__ a, const float* __restrict__ b,
                          const float* __restrict__ gam, const float* __restrict__ bet,
                          float* __restrict__ out, __half* __restrict__ out_h)
{
    const long row = blockIdx.x;
    const long base = row * Dm;
    __shared__ float sbuf[Dm];
    const int tid = threadIdx.x;

    float ls = 0.f;
    for (int j = tid; j < Dm; j += blockDim.x) {
        float x = a[base + j] + b[base + j];
        sbuf[j] = x;
        ls += x;
    }
    float mu = blockSum(ls) * (1.f / Dm);

    float lv = 0.f;
    for (int j = tid; j < Dm; j += blockDim.x) {
        float d = sbuf[j] - mu;
        lv += d * d;
    }
    float var = blockSum(lv) * (1.f / Dm);
    float inv = rsqrtf(var + EPS);

    for (int j = tid; j < Dm; j += blockDim.x) {
        float y = (sbuf[j] - mu) * inv * gam[j] + bet[j];
        out[base + j] = y;
        if (out_h) out_h[base + j] = __float2half_rn(y);
    }
}

// ---------------- launch ----------------------------------------------------
extern "C" void kernel_launch(void* const* d_in, const int* in_sizes, int n_in,
                              void* d_out, int out_size)
{
    const float* w      = (const float*)d_in[0];
    const float* r      = (const float*)d_in[1];
    const float* w_bias = (const float*)d_in[2];
    const float* r_bias = (const float*)d_in[3];
    const float* b1     = (const float*)d_in[12];
    const float* b2     = (const float*)d_in[14];
    const float* ln1g   = (const float*)d_in[9];
    const float* ln1b   = (const float*)d_in[10];
    const float* ln2g   = (const float*)d_in[15];
    const float* ln2b   = (const float*)d_in[16];
    float* out = (float*)d_out;

    float *ao, *x, *f;
    __half *qwh, *qrh, *kh, *vh, *rrh, *avh, *xh, *hh, *wh, *rh;
    __half *Wqt, *Wkt, *Wvt, *Wrt, *Wot, *W1t, *W2t;
    cudaGetSymbolAddress((void**)&ao,  g_ao);
    cudaGetSymbolAddress((void**)&x,   g_x);
    cudaGetSymbolAddress((void**)&f,   g_f);
    cudaGetSymbolAddress((void**)&qwh, g_qwh);
    cudaGetSymbolAddress((void**)&qrh, g_qrh);
    cudaGetSymbolAddress((void**)&kh,  g_kh);
    cudaGetSymbolAddress((void**)&vh,  g_vh);
    cudaGetSymbolAddress((void**)&rrh, g_rrh);
    cudaGetSymbolAddress((void**)&avh, g_avh);
    cudaGetSymbolAddress((void**)&xh,  g_xh);
    cudaGetSymbolAddress((void**)&hh,  g_hh);
    cudaGetSymbolAddress((void**)&wh,  g_wh);
    cudaGetSymbolAddress((void**)&rh,  g_rh);
    cudaGetSymbolAddress((void**)&Wqt, g_Wqt);
    cudaGetSymbolAddress((void**)&Wkt, g_Wkt);
    cudaGetSymbolAddress((void**)&Wvt, g_Wvt);
    cudaGetSymbolAddress((void**)&Wrt, g_Wrt);
    cudaGetSymbolAddress((void**)&Wot, g_Wot);
    cudaGetSymbolAddress((void**)&W1t, g_W1t);
    cudaGetSymbolAddress((void**)&W2t, g_W2t);

    const int M = Bq * Sq;

    // 0a) fp16 conversion of activations w, r
    roundh_kernel<<<dim3(512, 2), 256>>>((const float4*)w, wh,
                                         (const float4*)r, rh,
                                         Bq * Sq * Dm / 4);

    // 0b) transpose + fp16 of the 7 weights
    {
        T7 t{};
        const float* ins[7] = { (const float*)d_in[4], (const float*)d_in[5],
                                (const float*)d_in[6], (const float*)d_in[7],
                                (const float*)d_in[8], (const float*)d_in[11],
                                (const float*)d_in[13] };
        __half* outs[7] = { Wqt, Wkt, Wvt, Wrt, Wot, W1t, W2t };
        int Ks[7] = { Dm, Dm, Dm, Dm, Dm, Dm, DIf };
        int Ns[7] = { Dm, Dm, Dm, Dm, Dm, DIf, Dm };
        for (int i = 0; i < 7; i++) { t.in[i]=ins[i]; t.out[i]=outs[i]; t.K[i]=Ks[i]; t.N[i]=Ns[i]; }
        txp_kernel<<<dim3(128, 128, 7), 256>>>(t);
    }

    // 1) four projections -> fp16 outputs; q-biases fused (qw & qr dual)
    {
        SelH p{};
        p.A[0] = wh;  p.A[1] = wh;  p.A[2] = wh;  p.A[3] = rh;
        p.B[0] = Wqt; p.B[1] = Wkt; p.B[2] = Wvt; p.B[3] = Wrt;
        p.Ch[0] = qwh; p.Ch[1] = kh; p.Ch[2] = vh; p.Ch[3] = rrh;
        p.bias[0]  = w_bias;
        p.Ch2[0]   = qrh;
        p.bias2[0] = r_bias;
        launch_hg<false, 2>(dim3(Dm / 128, M / 128, 4), p, Dm, Dm);
    }

    // 2) fused fp16 flash attention
    cudaFuncSetAttribute(flash_kernel,
                         cudaFuncAttributeMaxDynamicSharedMemorySize, FLH_TOT);
    flash_kernel<<<512, 256, FLH_TOT>>>(qwh, qrh, kh, rrh, vh, avh);

    // 3) attn_out = av @ Wo (fp32 out)
    {
        SelH p{};
        p.A[0] = avh; p.B[0] = Wot; p.C[0] = ao;
        launch_hg<false, 0>(dim3(Dm / 128, M / 128, 1), p, Dm, Dm);
    }

    // 4) x = LN(w + attn_out); xh = fp16(x)
    ln_kernel<<<M, 256>>>(w, ao, ln1g, ln1b, x, xh);

    // 5) FFN: hh = fp16(relu(x @ W1 + b1)); f = hh @ W2 + b2
    {
        SelH p{};
        p.A[0] = xh; p.B[0] = W1t; p.bias[0] = b1; p.Ch[0] = hh;
        launch_hg<true, 2>(dim3(DIf / 128, M / 128, 1), p, Dm, DIf);
    }
    {
        SelH p{};
        p.A[0] = hh; p.B[0] = W2t; p.bias[0] = b2; p.C[0] = f;
        launch_hg<false, 0>(dim3(Dm / 128, M / 128, 1), p, DIf, Dm);
    }

    // 6) out = LN(x + f)
    ln_kernel<<<M, 256>>>(x, f, ln2g, ln2b, out, nullptr);
}

// round 16
// speedup vs baseline: 1.1822x; 1.0269x over previous
#include <cuda_runtime.h>
#include <cuda_fp16.h>
#include <math.h>
#include <cstdint>

// Problem constants
#define Bq  4
#define Sq  1024
#define Dm  1024
#define NHh 16
#define DHh 64
#define DIf 4096
#define EPS 1e-5f

// ---------------- scratch (static device globals; no allocations) ----------
__device__ float  g_ao[Bq*Sq*Dm];
__device__ float  g_x [Bq*Sq*Dm];
__device__ float  g_f [Bq*Sq*Dm];
// fp16 operands
__device__ __half g_qwh[Bq*Sq*Dm];
__device__ __half g_qrh[Bq*Sq*Dm];
__device__ __half g_kh [Bq*Sq*Dm];
__device__ __half g_vh [Bq*Sq*Dm];
__device__ __half g_rrh[Bq*Sq*Dm];
__device__ __half g_avh[Bq*Sq*Dm];
__device__ __half g_xh [Bq*Sq*Dm];
__device__ __half g_hh [Bq*Sq*DIf];
__device__ __half g_wh [Bq*Sq*Dm];
__device__ __half g_rh [Bq*Sq*Dm];
// weights TRANSPOSED ([N][K] row-major), fp16
__device__ __half g_Wqt[Dm*Dm];
__device__ __half g_Wkt[Dm*Dm];
__device__ __half g_Wvt[Dm*Dm];
__device__ __half g_Wrt[Dm*Dm];
__device__ __half g_Wot[Dm*Dm];
__device__ __half g_W1t[Dm*DIf];
__device__ __half g_W2t[DIf*Dm];

// ---------------- helpers ----------------------------------------------------
__device__ __forceinline__ void mma_f16(float* d, const uint4& a,
                                        uint32_t b0, uint32_t b1) {
    asm volatile(
        "mma.sync.aligned.m16n8k16.row.col.f32.f16.f16.f32 "
        "{%0,%1,%2,%3}, {%4,%5,%6,%7}, {%8,%9}, {%0,%1,%2,%3};"
        : "+f"(d[0]), "+f"(d[1]), "+f"(d[2]), "+f"(d[3])
        : "r"(a.x), "r"(a.y), "r"(a.z), "r"(a.w), "r"(b0), "r"(b1));
}

__device__ __forceinline__ uint4 ldsm4(unsigned addr) {
    uint4 d;
    asm volatile("ldmatrix.sync.aligned.m8n8.x4.shared.b16 {%0,%1,%2,%3}, [%4];"
                 : "=r"(d.x), "=r"(d.y), "=r"(d.z), "=r"(d.w) : "r"(addr));
    return d;
}

__device__ __forceinline__ uint4 ldsm4t(unsigned addr) {
    uint4 d;
    asm volatile("ldmatrix.sync.aligned.m8n8.x4.trans.shared.b16 {%0,%1,%2,%3}, [%4];"
                 : "=r"(d.x), "=r"(d.y), "=r"(d.z), "=r"(d.w) : "r"(addr));
    return d;
}

__device__ __forceinline__ void cp16(unsigned s, const void* g) {
    asm volatile("cp.async.cg.shared.global [%0], [%1], 16;" :: "r"(s), "l"(g));
}
#define CP_COMMIT()   asm volatile("cp.async.commit_group;")
#define CP_WAIT_ALL() asm volatile("cp.async.wait_all;" ::: "memory")

// ---------------- FP16 tensor-core GEMM (128x128, 2 BK=32 chunks/barrier) ---
struct SelH {
    const __half* A[4]; const __half* B[4];
    float* C[4]; const float* bias[4];
    float* C2[4]; const float* bias2[4];
    __half* Ch[4]; __half* Ch2[4];
};

#define HG_TILE  (128 * 80)
#define HG_STG   (2 * HG_TILE)
#define HG_SMEM  (4 * HG_STG)

template<bool RELU, int OUT>
__global__ void __launch_bounds__(256)
hg(SelH p, int K, int ldc)
{
    extern __shared__ __align__(16) char smraw[];
    const uint32_t sb = (uint32_t)__cvta_generic_to_shared(smraw);

    const int z   = blockIdx.z;
    const int tid = threadIdx.x, lane = tid & 31, wid = tid >> 5;
    const int warp_m = wid & 1, warp_n = wid >> 1;
    const long m0 = (long)blockIdx.y * 128, n0 = (long)blockIdx.x * 128;

    const __half* A  = p.A[z] + m0 * K;
    const __half* Bt = p.B[z] + n0 * K;
    const float* bias  = p.bias[z]  ? p.bias[z]  + n0 : nullptr;
    float*       C     = p.C[z]     ? p.C[z]     + m0 * ldc + n0 : nullptr;
    const float* bias2 = p.bias2[z] ? p.bias2[z] + n0 : nullptr;
    __half*      Ch    = p.Ch[z]    ? p.Ch[z]    + m0 * ldc + n0 : nullptr;
    __half*      Ch2   = p.Ch2[z]   ? p.Ch2[z]   + m0 * ldc + n0 : nullptr;

    float acc[4][4][4];
    #pragma unroll
    for (int i = 0; i < 4; i++)
        #pragma unroll
        for (int j = 0; j < 4; j++)
            #pragma unroll
            for (int l = 0; l < 4; l++) acc[i][j][l] = 0.f;

    const int ntile = K >> 5;

    auto issue = [&](int c) {
        const int st = c & 3;
        const int k0 = c << 5;
        const uint32_t ab = sb + (uint32_t)st * HG_STG;
        const uint32_t bb = ab + HG_TILE;
        #pragma unroll
        for (int i = 0; i < 2; i++) {
            int e = tid + i * 256;
            int row = e >> 2, sg = e & 3;
            cp16(ab + (uint32_t)(row * 80 + sg * 16),
                 &A[(long)row * K + k0 + sg * 8]);
        }
        #pragma unroll
        for (int i = 0; i < 2; i++) {
            int e = tid + i * 256;
            int row = e >> 2, sg = e & 3;
            cp16(bb + (uint32_t)(row * 80 + sg * 16),
                 &Bt[(long)row * K + k0 + sg * 8]);
        }
    };

    auto compute = [&](int st) {
        const uint32_t ab = sb + (uint32_t)st * HG_STG;
        const uint32_t bb = ab + HG_TILE;
        const int rw = lane & 7, grp = lane >> 3;
        const uint32_t acol = (uint32_t)((grp >> 1) * 16);
        const uint32_t rsel = (uint32_t)((grp & 1) * 8 + rw);
        #pragma unroll
        for (int kb = 0; kb < 2; kb++) {
            uint4 af[4];
            #pragma unroll
            for (int mt = 0; mt < 4; mt++)
                af[mt] = ldsm4(ab + (uint32_t)(warp_m * 64 + mt * 16 + rsel) * 80
                               + kb * 32 + acol);
            uint4 bq[2];
            #pragma unroll
            for (int nb = 0; nb < 2; nb++)
                bq[nb] = ldsm4(bb + (uint32_t)(warp_n * 32 + nb * 16 + rsel) * 80
                               + kb * 32 + acol);
            #pragma unroll
            for (int mt = 0; mt < 4; mt++)
                #pragma unroll
                for (int nt = 0; nt < 4; nt++) {
                    uint32_t b0 = (nt & 1) ? bq[nt >> 1].y : bq[nt >> 1].x;
                    uint32_t b1 = (nt & 1) ? bq[nt >> 1].w : bq[nt >> 1].z;
                    mma_f16(acc[mt][nt], af[mt], b0, b1);
                }
        }
    };

    issue(0); CP_COMMIT();
    if (ntile > 1) issue(1);
    CP_COMMIT();
    for (int t = 0; t < ntile; t += 2) {
        CP_WAIT_ALL();
        __syncthreads();
        if (t + 2 < ntile) issue(t + 2);
        CP_COMMIT();
        compute(t & 3);
        if (t + 3 < ntile) issue(t + 3);
        CP_COMMIT();
        if (t + 1 < ntile) compute((t + 1) & 3);
    }

    // ---- epilogue ----
    #pragma unroll
    for (int mt = 0; mt < 4; mt++) {
        int rbase = warp_m * 64 + mt * 16 + (lane >> 2);
        #pragma unroll
        for (int nt = 0; nt < 4; nt++) {
            int cbase = warp_n * 32 + nt * 8 + (lane & 3) * 2;
            float* d = acc[mt][nt];
            float b0 = 0.f, b1 = 0.f;
            if (bias) { b0 = bias[cbase]; b1 = bias[cbase + 1]; }
            float v0 = d[0] + b0, v1 = d[1] + b1;
            float v2 = d[2] + b0, v3 = d[3] + b1;
            if (RELU) {
                v0 = fmaxf(v0, 0.f); v1 = fmaxf(v1, 0.f);
                v2 = fmaxf(v2, 0.f); v3 = fmaxf(v3, 0.f);
            }
            if (OUT == 2) {
                *(__half2*)&Ch[(long)rbase * ldc + cbase]       = __floats2half2_rn(v0, v1);
                *(__half2*)&Ch[(long)(rbase + 8) * ldc + cbase] = __floats2half2_rn(v2, v3);
                if (Ch2) {
                    float c0 = bias2[cbase], c1 = bias2[cbase + 1];
                    *(__half2*)&Ch2[(long)rbase * ldc + cbase] =
                        __floats2half2_rn(d[0] + c0, d[1] + c1);
                    *(__half2*)&Ch2[(long)(rbase + 8) * ldc + cbase] =
                        __floats2half2_rn(d[2] + c0, d[3] + c1);
                }
            } else {
                *(float2*)&C[(long)rbase * ldc + cbase]       = make_float2(v0, v1);
                *(float2*)&C[(long)(rbase + 8) * ldc + cbase] = make_float2(v2, v3);
            }
        }
    }
}

template<bool RELU, int OUT>
static void launch_hg(dim3 grid, const SelH& p, int K, int ldc)
{
    cudaFuncSetAttribute(hg<RELU, OUT>,
                         cudaFuncAttributeMaxDynamicSharedMemorySize, HG_SMEM);
    hg<RELU, OUT><<<grid, 256, HG_SMEM>>>(p, K, ldc);
}

// ---------------- input conversion passes ------------------------------------
__global__ void roundh_kernel(const float4* __restrict__ s0, __half* __restrict__ d0,
                              const float4* __restrict__ s1, __half* __restrict__ d1,
                              int n4) {
    const float4* s = blockIdx.y ? s1 : s0;
    __half*       d = blockIdx.y ? d1 : d0;
    for (int i = blockIdx.x * blockDim.x + threadIdx.x; i < n4;
         i += gridDim.x * blockDim.x) {
        float4 v = s[i];
        *(__half2*)&d[4 * i]     = __floats2half2_rn(v.x, v.y);
        *(__half2*)&d[4 * i + 2] = __floats2half2_rn(v.z, v.w);
    }
}

// Flattened weight transpose: exact tile list (no dead blocks).
// z 0..4: 1024 tiles each (32x32 of 1024x1024); z5 (W1): 4096; z6 (W2): 4096.
struct T7 { const float* in[7]; __half* out[7]; };

__global__ void txp_kernel(T7 t) {
    __shared__ float tb[32][33];
    int bx = blockIdx.x;
    int z, tix, K_, N_;
    if (bx < 5120)      { z = bx >> 10; tix = bx & 1023; K_ = Dm;  N_ = Dm;  }
    else if (bx < 9216) { z = 5; tix = bx - 5120;        K_ = Dm;  N_ = DIf; }
    else                { z = 6; tix = bx - 9216;        K_ = DIf; N_ = Dm;  }
    const int ntx = N_ >> 5;
    const int n0 = (tix % ntx) * 32, k0 = (tix / ntx) * 32;
    const int tx = threadIdx.x & 31, ty = threadIdx.x >> 5;
    #pragma unroll
    for (int i = 0; i < 32; i += 8)
        tb[ty + i][tx] = t.in[z][(long)(k0 + ty + i) * N_ + n0 + tx];
    __syncthreads();
    #pragma unroll
    for (int i = 0; i < 32; i += 8)
        t.out[z][(long)(n0 + ty + i) * K_ + k0 + tx] = __float2half_rn(tb[tx][ty + i]);
}

// ---------------- fused fp16 flash attention with rel-shift -------------------
// One CTA = 128 query rows of one (b,h). All MMAs m16n8k16 fp16, fp32 accum.
// V row-major; PV B-fragments via ldmatrix.trans. rr ring = 4 x 64 segments
// (slot = l & 255). E/P buffer padded to 136 halves/row with column base +32
// so E-band stores are UNCONDITIONAL (garbage lands outside read range [32,96)).
#define FLH_STB  144
#define FLH_PST  136              // P/E row stride in halves (272 B)
#define FLH_PBASE 32              // column base offset
#define FLH_KS   0
#define FLH_VT   9216
#define FLH_RR   18432
#define FLH_PB   55296
#define FLH_TOT  90112

__global__ void __launch_bounds__(256, 2)
flash_kernel(const __half* __restrict__ qwp, const __half* __restrict__ qrp,
             const __half* __restrict__ kp,  const __half* __restrict__ rp,
             const __half* __restrict__ vp,  __half* __restrict__ avph)
{
    extern __shared__ char smh[];
    __half* Ph = (__half*)(smh + FLH_PB);
    const uint32_t base = (uint32_t)__cvta_generic_to_shared(smh);
    const uint32_t sK = base + FLH_KS;
    const uint32_t sV = base + FLH_VT;
    const uint32_t sR = base + FLH_RR;
    const uint32_t sP = base + FLH_PB;

    const int bid = blockIdx.x;
    const int it  = 7 - (bid >> 6);           // heavy blocks first
    const int bh  = bid & 63;
    const int b   = bh >> 4, h = bh & 15;
    const int i0  = it * 128;

    const int tid = threadIdx.x, lane = tid & 31, wid = tid >> 5;
    const int r0w = wid * 16;
    const int grp = lane >> 3, rw = lane & 7;
    const int r = lane >> 2, c = lane & 3;
    const uint32_t rsel = (uint32_t)((grp & 1) * 8 + rw);
    const uint32_t acol = (uint32_t)((grp >> 1) * 16);

    const long qbase  = ((long)(b * Sq + i0)) * Dm + h * 64;
    const long kvbase = ((long)b * Sq) * Dm + h * 64;

    // ---- stage Q tiles (qw -> rr area, qr -> P area, stride 144) ----
    for (int e = tid; e < 128 * 8; e += 256) {
        int row = e >> 3, sg = e & 7;
        cp16(sR + (uint32_t)(row * FLH_STB + sg * 16), &qwp[qbase + (long)row * Dm + sg * 8]);
        cp16(sP + (uint32_t)(row * FLH_STB + sg * 16), &qrp[qbase + (long)row * Dm + sg * 8]);
    }
    CP_COMMIT(); CP_WAIT_ALL(); __syncthreads();
    uint4 qwf[4], qrf[4];
    #pragma unroll
    for (int kb = 0; kb < 4; kb++) {
        uint32_t off = (uint32_t)((r0w + rsel) * FLH_STB) + kb * 32 + acol;
        qwf[kb] = ldsm4(sR + off);
        qrf[kb] = ldsm4(sP + off);
    }
    __syncthreads();   // all Q fragments extracted before P area reuse

    float m0v = -1e30f, m1v = -1e30f, l0v = 0.f, l1v = 0.f;
    float o_[8][4];
    #pragma unroll
    for (int i = 0; i < 8; i++)
        #pragma unroll
        for (int j = 0; j < 4; j++) o_[i][j] = 0.f;

    const int njt = (i0 >> 6) + 2;
    for (int jt = 0; jt < njt; jt++) {
        const int j0 = jt * 64;
        const int l0 = Sq - 128 + j0 - i0;    // rr window base (64-aligned, >= 0)
        __syncthreads();                       // prev-tile smem reads done

        // K + V tiles (both row-major, cp.async)
        for (int e = tid; e < 64 * 8; e += 256) {
            int row = e >> 3, sg = e & 7;
            cp16(sK + (uint32_t)(row * FLH_STB + sg * 16),
                 &kp[kvbase + (long)(j0 + row) * Dm + sg * 8]);
            cp16(sV + (uint32_t)(row * FLH_STB + sg * 16),
                 &vp[kvbase + (long)(j0 + row) * Dm + sg * 8]);
        }
        // rr ring: first tile 192 rows; later only 64 new; slot = l & 255
        {
            int rlo = (jt == 0) ? 0 : 128;
            for (int e = tid + rlo * 8; e < 192 * 8; e += 256) {
                int row = e >> 3, sg = e & 7;
                int l = l0 + row;
                int slot = l & 255;
                int lr = l > Sq - 1 ? Sq - 1 : l;
                cp16(sR + (uint32_t)(slot * FLH_STB + sg * 16),
                     &rp[kvbase + (long)lr * Dm + sg * 8]);
            }
        }
        CP_COMMIT();
        CP_WAIT_ALL(); __syncthreads();

        // ---- E band MMA: unconditional padded stores ----
        {
            int dlo = 105 - r0w; if (dlo < 0) dlo = 0; dlo &= ~7;
            int dhi = (190 - r0w) & ~7;
            for (int d0 = dlo; d0 <= dhi; d0 += 16) {
                bool has2 = (d0 + 8 <= dhi);
                float e0[4] = {0.f,0.f,0.f,0.f}, e1[4] = {0.f,0.f,0.f,0.f};
                int lb = l0 + d0 + (grp & 1) * 8;
                int slotb = lb & 255;
                #pragma unroll
                for (int kb = 0; kb < 4; kb++) {
                    uint4 bf = ldsm4(sR + (uint32_t)((slotb + rw) * FLH_STB)
                                     + kb * 32 + acol);
                    mma_f16(e0, qrf[kb], bf.x, bf.z);
                    if (has2) mma_f16(e1, qrf[kb], bf.y, bf.w);
                }
                int ii0 = r0w + r, ii1 = ii0 + 8;
                int d = d0 + 2 * c;
                int ja = d - 127 + ii0 + FLH_PBASE;   // in [3, ...]
                int jb = d - 127 + ii1 + FLH_PBASE;
                Ph[ii0 * FLH_PST + ja    ] = __float2half_rn(e0[0]);
                Ph[ii0 * FLH_PST + ja + 1] = __float2half_rn(e0[1]);
                Ph[ii1 * FLH_PST + jb    ] = __float2half_rn(e0[2]);
                Ph[ii1 * FLH_PST + jb + 1] = __float2half_rn(e0[3]);
                if (has2) {
                    Ph[ii0 * FLH_PST + ja + 8] = __float2half_rn(e1[0]);
                    Ph[ii0 * FLH_PST + ja + 9] = __float2half_rn(e1[1]);
                    Ph[ii1 * FLH_PST + jb + 8] = __float2half_rn(e1[2]);
                    Ph[ii1 * FLH_PST + jb + 9] = __float2half_rn(e1[3]);
                }
            }
        }
        __syncwarp();   // band written by this warp's lanes, read below

        // ---- ac MMA (fp16) ----
        float s_[8][4];
        #pragma unroll
        for (int i = 0; i < 8; i++)
            #pragma unroll
            for (int j = 0; j < 4; j++) s_[i][j] = 0.f;
        #pragma unroll
        for (int kb = 0; kb < 4; kb++) {
            #pragma unroll
            for (int nb = 0; nb < 4; nb++) {
                uint4 bq = ldsm4(sK + (uint32_t)((nb * 16 + rsel) * FLH_STB)
                                 + kb * 32 + acol);
                mma_f16(s_[2 * nb],     qwf[kb], bq.x, bq.z);
                mma_f16(s_[2 * nb + 1], qwf[kb], bq.y, bq.w);
            }
        }

        // ---- S = (ac + E)*scale, mask, online softmax ----
        const int gi0 = i0 + r0w + r, gi1 = gi0 + 8;
        float mx0 = -1e30f, mx1 = -1e30f;
        #pragma unroll
        for (int nt = 0; nt < 8; nt++) {
            int jj = nt * 8 + 2 * c, jg = j0 + jj;
            float e00 = __half2float(Ph[(r0w + r) * FLH_PST + FLH_PBASE + jj]);
            float e01 = __half2float(Ph[(r0w + r) * FLH_PST + FLH_PBASE + jj + 1]);
            float e10 = __half2float(Ph[(r0w + r + 8) * FLH_PST + FLH_PBASE + jj]);
            float e11 = __half2float(Ph[(r0w + r + 8) * FLH_PST + FLH_PBASE + jj + 1]);
            s_[nt][0] = (jg     <= gi0) ? (s_[nt][0] + e00) * 0.125f : -1e30f;
            s_[nt][1] = (jg + 1 <= gi0) ? (s_[nt][1] + e01) * 0.125f : -1e30f;
            s_[nt][2] = (jg     <= gi1) ? (s_[nt][2] + e10) * 0.125f : -1e30f;
            s_[nt][3] = (jg + 1 <= gi1) ? (s_[nt][3] + e11) * 0.125f : -1e30f;
            mx0 = fmaxf(mx0, fmaxf(s_[nt][0], s_[nt][1]));
            mx1 = fmaxf(mx1, fmaxf(s_[nt][2], s_[nt][3]));
        }
        mx0 = fmaxf(mx0, __shfl_xor_sync(0xffffffffu, mx0, 1));
        mx0 = fmaxf(mx0, __shfl_xor_sync(0xffffffffu, mx0, 2));
        mx1 = fmaxf(mx1, __shfl_xor_sync(0xffffffffu, mx1, 1));
        mx1 = fmaxf(mx1, __shfl_xor_sync(0xffffffffu, mx1, 2));
        float mn0 = fmaxf(m0v, mx0), mn1 = fmaxf(m1v, mx1);
        float a0 = __expf(m0v - mn0), a1 = __expf(m1v - mn1);
        float sum0 = 0.f, sum1 = 0.f;
        #pragma unroll
        for (int nt = 0; nt < 8; nt++) {
            int jj = nt * 8 + 2 * c;
            float p00 = __expf(s_[nt][0] - mn0), p01 = __expf(s_[nt][1] - mn0);
            float p10 = __expf(s_[nt][2] - mn1), p11 = __expf(s_[nt][3] - mn1);
            sum0 += p00 + p01; sum1 += p10 + p11;
            *(__half2*)&Ph[(r0w + r) * FLH_PST + FLH_PBASE + jj]     = __floats2half2_rn(p00, p01);
            *(__half2*)&Ph[(r0w + r + 8) * FLH_PST + FLH_PBASE + jj] = __floats2half2_rn(p10, p11);
        }
        sum0 += __shfl_xor_sync(0xffffffffu, sum0, 1);
        sum0 += __shfl_xor_sync(0xffffffffu, sum0, 2);
        sum1 += __shfl_xor_sync(0xffffffffu, sum1, 1);
        sum1 += __shfl_xor_sync(0xffffffffu, sum1, 2);
        l0v = l0v * a0 + sum0; l1v = l1v * a1 + sum1;
        m0v = mn0; m1v = mn1;
        #pragma unroll
        for (int dt = 0; dt < 8; dt++) {
            o_[dt][0] *= a0; o_[dt][1] *= a0;
            o_[dt][2] *= a1; o_[dt][3] *= a1;
        }
        __syncwarp();   // P written by this warp, read via ldmatrix below

        // ---- PV: O += P @ V (fp16); V^T fragments via ldmatrix.trans ----
        #pragma unroll
        for (int kb = 0; kb < 4; kb++) {
            uint4 af = ldsm4(sP + (uint32_t)((r0w + rsel) * FLH_PST * 2)
                             + FLH_PBASE * 2 + kb * 32 + acol);
            #pragma unroll
            for (int nb = 0; nb < 4; nb++) {
                uint4 bq = ldsm4t(sV + (uint32_t)((kb * 16 + (grp & 1) * 8 + rw) * FLH_STB)
                                  + nb * 32 + (grp >> 1) * 16);
                mma_f16(o_[2 * nb],     af, bq.x, bq.y);
                mma_f16(o_[2 * nb + 1], af, bq.z, bq.w);
            }
        }
    }

    // ---- epilogue: O / l, fp16 (feeds Wo hgemm) ----
    float i0v = 1.f / l0v, i1v = 1.f / l1v;
    long ob0 = ((long)(b * Sq + i0 + r0w + r)) * Dm + h * 64;
    long ob1 = ob0 + 8L * Dm;
    #pragma unroll
    for (int dt = 0; dt < 8; dt++) {
        int d = dt * 8 + 2 * c;
        *(__half2*)&avph[ob0 + d] = __floats2half2_rn(o_[dt][0] * i0v, o_[dt][1] * i0v);
        *(__half2*)&avph[ob1 + d] = __floats2half2_rn(o_[dt][2] * i1v, o_[dt][3] * i1v);
    }
}

// ---------------- reductions / LN --------------------------------------------
__device__ __forceinline__ float warpSum(float v) {
    #pragma unroll
    for (int o = 16; o > 0; o >>= 1) v += __shfl_xor_sync(0xffffffffu, v, o);
    return v;
}
__device__ float blockSum(float v) {
    __shared__ float red[8];
    __syncthreads();
    int lane = threadIdx.x & 31, wid = threadIdx.x >> 5;
    v = warpSum(v);
    if (lane == 0) red[wid] = v;
    __syncthreads();
    if (wid == 0) {
        float t = (lane < 8) ? red[lane] : 0.f;
        t = warpSum(t);
        if (lane == 0) red[0] = t;
    }
    __syncthreads();
    return red[0];
}

// Vectorized LN: one float4 per thread (Dm = 256 threads * 4), row in regs.
__global__ void ln_kernel(const float4* __restrict__ a, const float4* __restrict__ b,
                          const float4* __restrict__ gam, const float4* __restrict__ bet,
                          float4* __restrict__ out, __half* __restrict__ out_h)
{
    const long row = blockIdx.x;
    const int tid = threadIdx.x;
    const long idx = row * 256 + tid;

    float4 va = a[idx], vb = b[idx];
    float4 xv = make_float4(va.x + vb.x, va.y + vb.y, va.z + vb.z, va.w + vb.w);

    float mu = blockSum(xv.x + xv.y + xv.z + xv.w) * (1.f / Dm);
    float dx = xv.x - mu, dy = xv.y - mu, dz = xv.z - mu, dw = xv.w - mu;
    float var = blockSum(dx * dx + dy * dy + dz * dz + dw * dw) * (1.f / Dm);
    float inv = rsqrtf(var + EPS);

    float4 g = gam[tid], be = bet[tid];
    float4 y = make_float4(dx * inv * g.x + be.x, dy * inv * g.y + be.y,
                           dz * inv * g.z + be.z, dw * inv * g.w + be.w);
    out[idx] = y;
    if (out_h) {
        *(__half2*)&out_h[4 * idx]     = __floats2half2_rn(y.x, y.y);
        *(__half2*)&out_h[4 * idx + 2] = __floats2half2_rn(y.z, y.w);
    }
}

// ---------------- launch ----------------------------------------------------
extern "C" void kernel_launch(void* const* d_in, const int* in_sizes, int n_in,
                              void* d_out, int out_size)
{
    const float* w      = (const float*)d_in[0];
    const float* r      = (const float*)d_in[1];
    const float* w_bias = (const float*)d_in[2];
    const float* r_bias = (const float*)d_in[3];
    const float* b1     = (const float*)d_in[12];
    const float* b2     = (const float*)d_in[14];
    const float* ln1g   = (const float*)d_in[9];
    const float* ln1b   = (const float*)d_in[10];
    const float* ln2g   = (const float*)d_in[15];
    const float* ln2b   = (const float*)d_in[16];
    float* out = (float*)d_out;

    float *ao, *x, *f;
    __half *qwh, *qrh, *kh, *vh, *rrh, *avh, *xh, *hh, *wh, *rh;
    __half *Wqt, *Wkt, *Wvt, *Wrt, *Wot, *W1t, *W2t;
    cudaGetSymbolAddress((void**)&ao,  g_ao);
    cudaGetSymbolAddress((void**)&x,   g_x);
    cudaGetSymbolAddress((void**)&f,   g_f);
    cudaGetSymbolAddress((void**)&qwh, g_qwh);
    cudaGetSymbolAddress((void**)&qrh, g_qrh);
    cudaGetSymbolAddress((void**)&kh,  g_kh);
    cudaGetSymbolAddress((void**)&vh,  g_vh);
    cudaGetSymbolAddress((void**)&rrh, g_rrh);
    cudaGetSymbolAddress((void**)&avh, g_avh);
    cudaGetSymbolAddress((void**)&xh,  g_xh);
    cudaGetSymbolAddress((void**)&hh,  g_hh);
    cudaGetSymbolAddress((void**)&wh,  g_wh);
    cudaGetSymbolAddress((void**)&rh,  g_rh);
    cudaGetSymbolAddress((void**)&Wqt, g_Wqt);
    cudaGetSymbolAddress((void**)&Wkt, g_Wkt);
    cudaGetSymbolAddress((void**)&Wvt, g_Wvt);
    cudaGetSymbolAddress((void**)&Wrt, g_Wrt);
    cudaGetSymbolAddress((void**)&Wot, g_Wot);
    cudaGetSymbolAddress((void**)&W1t, g_W1t);
    cudaGetSymbolAddress((void**)&W2t, g_W2t);

    const int M = Bq * Sq;

    // 0a) fp16 conversion of activations w, r
    roundh_kernel<<<dim3(512, 2), 256>>>((const float4*)w, wh,
                                         (const float4*)r, rh,
                                         Bq * Sq * Dm / 4);

    // 0b) transpose + fp16 of the 7 weights (flattened exact grid)
    {
        T7 t{};
        const float* ins[7] = { (const float*)d_in[4], (const float*)d_in[5],
                                (const float*)d_in[6], (const float*)d_in[7],
                                (const float*)d_in[8], (const float*)d_in[11],
                                (const float*)d_in[13] };
        __half* outs[7] = { Wqt, Wkt, Wvt, Wrt, Wot, W1t, W2t };
        for (int i = 0; i < 7; i++) { t.in[i] = ins[i]; t.out[i] = outs[i]; }
        txp_kernel<<<13312, 256>>>(t);
    }

    // 1) four projections -> fp16 outputs; q-biases fused (qw & qr dual)
    {
        SelH p{};
        p.A[0] = wh;  p.A[1] = wh;  p.A[2] = wh;  p.A[3] = rh;
        p.B[0] = Wqt; p.B[1] = Wkt; p.B[2] = Wvt; p.B[3] = Wrt;
        p.Ch[0] = qwh; p.Ch[1] = kh; p.Ch[2] = vh; p.Ch[3] = rrh;
        p.bias[0]  = w_bias;
        p.Ch2[0]   = qrh;
        p.bias2[0] = r_bias;
        launch_hg<false, 2>(dim3(Dm / 128, M / 128, 4), p, Dm, Dm);
    }

    // 2) fused fp16 flash attention
    cudaFuncSetAttribute(flash_kernel,
                         cudaFuncAttributeMaxDynamicSharedMemorySize, FLH_TOT);
    flash_kernel<<<512, 256, FLH_TOT>>>(qwh, qrh, kh, rrh, vh, avh);

    // 3) attn_out = av @ Wo (fp32 out)
    {
        SelH p{};
        p.A[0] = avh; p.B[0] = Wot; p.C[0] = ao;
        launch_hg<false, 0>(dim3(Dm / 128, M / 128, 1), p, Dm, Dm);
    }

    // 4) x = LN(w + attn_out); xh = fp16(x)
    ln_kernel<<<M, 256>>>((const float4*)w, (const float4*)ao,
                          (const float4*)ln1g, (const float4*)ln1b,
                          (float4*)x, xh);

    // 5) FFN: hh = fp16(relu(x @ W1 + b1)); f = hh @ W2 + b2
    {
        SelH p{};
        p.A[0] = xh; p.B[0] = W1t; p.bias[0] = b1; p.Ch[0] = hh;
        launch_hg<true, 2>(dim3(DIf / 128, M / 128, 1), p, Dm, DIf);
    }
    {
        SelH p{};
        p.A[0] = hh; p.B[0] = W2t; p.bias[0] = b2; p.C[0] = f;
        launch_hg<false, 0>(dim3(Dm / 128, M / 128, 1), p, DIf, Dm);
    }

    // 6) out = LN(x + f)
    ln_kernel<<<M, 256>>>((const float4*)x, (const float4*)f,
                          (const float4*)ln2g, (const float4*)ln2b,
                          (float4*)out, nullptr);
}

// round 17
// speedup vs baseline: 1.1933x; 1.0094x over previous
#include <cuda_runtime.h>
#include <cuda_fp16.h>
#include <math.h>
#include <cstdint>

// Problem constants
#define Bq  4
#define Sq  1024
#define Dm  1024
#define NHh 16
#define DHh 64
#define DIf 4096
#define EPS 1e-5f

// ---------------- scratch (static device globals; no allocations) ----------
__device__ float  g_ao[Bq*Sq*Dm];
__device__ float  g_x [Bq*Sq*Dm];
__device__ float  g_f [Bq*Sq*Dm];
// fp16 operands
__device__ __half g_qwh[Bq*Sq*Dm];
__device__ __half g_qrh[Bq*Sq*Dm];
__device__ __half g_kh [Bq*Sq*Dm];
__device__ __half g_vh [Bq*Sq*Dm];
__device__ __half g_rrh[Bq*Sq*Dm];
__device__ __half g_avh[Bq*Sq*Dm];
__device__ __half g_xh [Bq*Sq*Dm];
__device__ __half g_hh [Bq*Sq*DIf];
__device__ __half g_wh [Bq*Sq*Dm];
__device__ __half g_rh [Bq*Sq*Dm];
// weights TRANSPOSED ([N][K] row-major), fp16
__device__ __half g_Wqt[Dm*Dm];
__device__ __half g_Wkt[Dm*Dm];
__device__ __half g_Wvt[Dm*Dm];
__device__ __half g_Wrt[Dm*Dm];
__device__ __half g_Wot[Dm*Dm];
__device__ __half g_W1t[Dm*DIf];
__device__ __half g_W2t[DIf*Dm];

// ---------------- helpers ----------------------------------------------------
__device__ __forceinline__ void mma_f16(float* d, const uint4& a,
                                        uint32_t b0, uint32_t b1) {
    asm volatile(
        "mma.sync.aligned.m16n8k16.row.col.f32.f16.f16.f32 "
        "{%0,%1,%2,%3}, {%4,%5,%6,%7}, {%8,%9}, {%0,%1,%2,%3};"
        : "+f"(d[0]), "+f"(d[1]), "+f"(d[2]), "+f"(d[3])
        : "r"(a.x), "r"(a.y), "r"(a.z), "r"(a.w), "r"(b0), "r"(b1));
}

__device__ __forceinline__ uint4 ldsm4(unsigned addr) {
    uint4 d;
    asm volatile("ldmatrix.sync.aligned.m8n8.x4.shared.b16 {%0,%1,%2,%3}, [%4];"
                 : "=r"(d.x), "=r"(d.y), "=r"(d.z), "=r"(d.w) : "r"(addr));
    return d;
}

__device__ __forceinline__ uint4 ldsm4t(unsigned addr) {
    uint4 d;
    asm volatile("ldmatrix.sync.aligned.m8n8.x4.trans.shared.b16 {%0,%1,%2,%3}, [%4];"
                 : "=r"(d.x), "=r"(d.y), "=r"(d.z), "=r"(d.w) : "r"(addr));
    return d;
}

__device__ __forceinline__ void cp16(unsigned s, const void* g) {
    asm volatile("cp.async.cg.shared.global [%0], [%1], 16;" :: "r"(s), "l"(g));
}
#define CP_COMMIT()   asm volatile("cp.async.commit_group;")
#define CP_WAIT_ALL() asm volatile("cp.async.wait_all;" ::: "memory")

// ---------------- FP16 tensor-core GEMM (128x128, 2 BK=32 chunks/barrier) ---
struct SelH {
    const __half* A[4]; const __half* B[4];
    float* C[4]; const float* bias[4];
    float* C2[4]; const float* bias2[4];
    __half* Ch[4]; __half* Ch2[4];
};

#define HG_TILE  (128 * 80)
#define HG_STG   (2 * HG_TILE)
#define HG_SMEM  (4 * HG_STG)

template<bool RELU, int OUT>
__global__ void __launch_bounds__(256)
hg(SelH p, int K, int ldc)
{
    extern __shared__ __align__(16) char smraw[];
    const uint32_t sb = (uint32_t)__cvta_generic_to_shared(smraw);

    const int z   = blockIdx.z;
    const int tid = threadIdx.x, lane = tid & 31, wid = tid >> 5;
    const int warp_m = wid & 1, warp_n = wid >> 1;
    const long m0 = (long)blockIdx.y * 128, n0 = (long)blockIdx.x * 128;

    const __half* A  = p.A[z] + m0 * K;
    const __half* Bt = p.B[z] + n0 * K;
    const float* bias  = p.bias[z]  ? p.bias[z]  + n0 : nullptr;
    float*       C     = p.C[z]     ? p.C[z]     + m0 * ldc + n0 : nullptr;
    const float* bias2 = p.bias2[z] ? p.bias2[z] + n0 : nullptr;
    __half*      Ch    = p.Ch[z]    ? p.Ch[z]    + m0 * ldc + n0 : nullptr;
    __half*      Ch2   = p.Ch2[z]   ? p.Ch2[z]   + m0 * ldc + n0 : nullptr;

    float acc[4][4][4];
    #pragma unroll
    for (int i = 0; i < 4; i++)
        #pragma unroll
        for (int j = 0; j < 4; j++)
            #pragma unroll
            for (int l = 0; l < 4; l++) acc[i][j][l] = 0.f;

    const int ntile = K >> 5;

    auto issue = [&](int c) {
        const int st = c & 3;
        const int k0 = c << 5;
        const uint32_t ab = sb + (uint32_t)st * HG_STG;
        const uint32_t bb = ab + HG_TILE;
        #pragma unroll
        for (int i = 0; i < 2; i++) {
            int e = tid + i * 256;
            int row = e >> 2, sg = e & 3;
            cp16(ab + (uint32_t)(row * 80 + sg * 16),
                 &A[(long)row * K + k0 + sg * 8]);
        }
        #pragma unroll
        for (int i = 0; i < 2; i++) {
            int e = tid + i * 256;
            int row = e >> 2, sg = e & 3;
            cp16(bb + (uint32_t)(row * 80 + sg * 16),
                 &Bt[(long)row * K + k0 + sg * 8]);
        }
    };

    auto compute = [&](int st) {
        const uint32_t ab = sb + (uint32_t)st * HG_STG;
        const uint32_t bb = ab + HG_TILE;
        const int rw = lane & 7, grp = lane >> 3;
        const uint32_t acol = (uint32_t)((grp >> 1) * 16);
        const uint32_t rsel = (uint32_t)((grp & 1) * 8 + rw);
        #pragma unroll
        for (int kb = 0; kb < 2; kb++) {
            uint4 af[4];
            #pragma unroll
            for (int mt = 0; mt < 4; mt++)
                af[mt] = ldsm4(ab + (uint32_t)(warp_m * 64 + mt * 16 + rsel) * 80
                               + kb * 32 + acol);
            uint4 bq[2];
            #pragma unroll
            for (int nb = 0; nb < 2; nb++)
                bq[nb] = ldsm4(bb + (uint32_t)(warp_n * 32 + nb * 16 + rsel) * 80
                               + kb * 32 + acol);
            #pragma unroll
            for (int mt = 0; mt < 4; mt++)
                #pragma unroll
                for (int nt = 0; nt < 4; nt++) {
                    uint32_t b0 = (nt & 1) ? bq[nt >> 1].y : bq[nt >> 1].x;
                    uint32_t b1 = (nt & 1) ? bq[nt >> 1].w : bq[nt >> 1].z;
                    mma_f16(acc[mt][nt], af[mt], b0, b1);
                }
        }
    };

    issue(0); CP_COMMIT();
    if (ntile > 1) issue(1);
    CP_COMMIT();
    for (int t = 0; t < ntile; t += 2) {
        CP_WAIT_ALL();
        __syncthreads();
        if (t + 2 < ntile) issue(t + 2);
        CP_COMMIT();
        compute(t & 3);
        if (t + 3 < ntile) issue(t + 3);
        CP_COMMIT();
        if (t + 1 < ntile) compute((t + 1) & 3);
    }

    // ---- epilogue ----
    // When Ch2 is set (q projection) both outputs are pre-scaled by 1/8
    // (exact power-of-two in fp16) so flash skips the softmax scale.
    const float sc = (OUT == 2 && Ch2) ? 0.125f : 1.0f;
    #pragma unroll
    for (int mt = 0; mt < 4; mt++) {
        int rbase = warp_m * 64 + mt * 16 + (lane >> 2);
        #pragma unroll
        for (int nt = 0; nt < 4; nt++) {
            int cbase = warp_n * 32 + nt * 8 + (lane & 3) * 2;
            float* d = acc[mt][nt];
            float b0 = 0.f, b1 = 0.f;
            if (bias) { b0 = bias[cbase]; b1 = bias[cbase + 1]; }
            float v0 = d[0] + b0, v1 = d[1] + b1;
            float v2 = d[2] + b0, v3 = d[3] + b1;
            if (RELU) {
                v0 = fmaxf(v0, 0.f); v1 = fmaxf(v1, 0.f);
                v2 = fmaxf(v2, 0.f); v3 = fmaxf(v3, 0.f);
            }
            if (OUT == 2) {
                *(__half2*)&Ch[(long)rbase * ldc + cbase]       = __floats2half2_rn(v0 * sc, v1 * sc);
                *(__half2*)&Ch[(long)(rbase + 8) * ldc + cbase] = __floats2half2_rn(v2 * sc, v3 * sc);
                if (Ch2) {
                    float c0 = bias2[cbase], c1 = bias2[cbase + 1];
                    *(__half2*)&Ch2[(long)rbase * ldc + cbase] =
                        __floats2half2_rn((d[0] + c0) * sc, (d[1] + c1) * sc);
                    *(__half2*)&Ch2[(long)(rbase + 8) * ldc + cbase] =
                        __floats2half2_rn((d[2] + c0) * sc, (d[3] + c1) * sc);
                }
            } else {
                *(float2*)&C[(long)rbase * ldc + cbase]       = make_float2(v0, v1);
                *(float2*)&C[(long)(rbase + 8) * ldc + cbase] = make_float2(v2, v3);
            }
        }
    }
}

template<bool RELU, int OUT>
static void launch_hg(dim3 grid, const SelH& p, int K, int ldc)
{
    cudaFuncSetAttribute(hg<RELU, OUT>,
                         cudaFuncAttributeMaxDynamicSharedMemorySize, HG_SMEM);
    hg<RELU, OUT><<<grid, 256, HG_SMEM>>>(p, K, ldc);
}

// ---------------- input conversion passes ------------------------------------
__global__ void roundh_kernel(const float4* __restrict__ s0, __half* __restrict__ d0,
                              const float4* __restrict__ s1, __half* __restrict__ d1,
                              int n4) {
    const float4* s = blockIdx.y ? s1 : s0;
    __half*       d = blockIdx.y ? d1 : d0;
    for (int i = blockIdx.x * blockDim.x + threadIdx.x; i < n4;
         i += gridDim.x * blockDim.x) {
        float4 v = s[i];
        *(__half2*)&d[4 * i]     = __floats2half2_rn(v.x, v.y);
        *(__half2*)&d[4 * i + 2] = __floats2half2_rn(v.z, v.w);
    }
}

// Flattened weight transpose: exact tile list (no dead blocks).
struct T7 { const float* in[7]; __half* out[7]; };

__global__ void txp_kernel(T7 t) {
    __shared__ float tb[32][33];
    int bx = blockIdx.x;
    int z, tix, K_, N_;
    if (bx < 5120)      { z = bx >> 10; tix = bx & 1023; K_ = Dm;  N_ = Dm;  }
    else if (bx < 9216) { z = 5; tix = bx - 5120;        K_ = Dm;  N_ = DIf; }
    else                { z = 6; tix = bx - 9216;        K_ = DIf; N_ = Dm;  }
    const int ntx = N_ >> 5;
    const int n0 = (tix % ntx) * 32, k0 = (tix / ntx) * 32;
    const int tx = threadIdx.x & 31, ty = threadIdx.x >> 5;
    #pragma unroll
    for (int i = 0; i < 32; i += 8)
        tb[ty + i][tx] = t.in[z][(long)(k0 + ty + i) * N_ + n0 + tx];
    __syncthreads();
    #pragma unroll
    for (int i = 0; i < 32; i += 8)
        t.out[z][(long)(n0 + ty + i) * K_ + k0 + tx] = __float2half_rn(tb[tx][ty + i]);
}

// ---------------- fused fp16 flash attention with rel-shift -------------------
// One CTA = 128 query rows of one (b,h). All MMAs m16n8k16 fp16, fp32 accum.
// 2-stage tile pipeline: K/V double-buffered; rr ring (256 rows) prefetches
// the 64 new rows for tile t+1 into its free segment during compute of tile t.
// q operands arrive pre-scaled by 1/8 (folded in projection epilogue).
// smem (bytes): K[2][64]x144 | V[2][64]x144 | rr[256]x144 | P/E[128]x272
#define FLH_STB  144
#define FLH_PST  136              // P/E row stride in halves (272 B)
#define FLH_PBASE 32
#define FLH_RR   36864
#define FLH_PB   73728
#define FLH_TOT  108544

__global__ void __launch_bounds__(256, 2)
flash_kernel(const __half* __restrict__ qwp, const __half* __restrict__ qrp,
             const __half* __restrict__ kp,  const __half* __restrict__ rp,
             const __half* __restrict__ vp,  __half* __restrict__ avph)
{
    extern __shared__ char smh[];
    __half* Ph = (__half*)(smh + FLH_PB);
    const uint32_t base = (uint32_t)__cvta_generic_to_shared(smh);
    const uint32_t sKb = base;            // 2 x 9216
    const uint32_t sVb = base + 18432;    // 2 x 9216
    const uint32_t sR  = base + FLH_RR;
    const uint32_t sP  = base + FLH_PB;

    const int bid = blockIdx.x;
    const int it  = 7 - (bid >> 6);           // heavy blocks first
    const int bh  = bid & 63;
    const int b   = bh >> 4, h = bh & 15;
    const int i0  = it * 128;

    const int tid = threadIdx.x, lane = tid & 31, wid = tid >> 5;
    const int r0w = wid * 16;
    const int grp = lane >> 3, rw = lane & 7;
    const int r = lane >> 2, c = lane & 3;
    const uint32_t rsel = (uint32_t)((grp & 1) * 8 + rw);
    const uint32_t acol = (uint32_t)((grp >> 1) * 16);

    const long qbase  = ((long)(b * Sq + i0)) * Dm + h * 64;
    const long kvbase = ((long)b * Sq) * Dm + h * 64;

    // ---- stage Q tiles (qw -> rr area, qr -> P area, stride 144) ----
    for (int e = tid; e < 128 * 8; e += 256) {
        int row = e >> 3, sg = e & 7;
        cp16(sR + (uint32_t)(row * FLH_STB + sg * 16), &qwp[qbase + (long)row * Dm + sg * 8]);
        cp16(sP + (uint32_t)(row * FLH_STB + sg * 16), &qrp[qbase + (long)row * Dm + sg * 8]);
    }
    CP_COMMIT(); CP_WAIT_ALL(); __syncthreads();
    uint4 qwf[4], qrf[4];
    #pragma unroll
    for (int kb = 0; kb < 4; kb++) {
        uint32_t off = (uint32_t)((r0w + rsel) * FLH_STB) + kb * 32 + acol;
        qwf[kb] = ldsm4(sR + off);
        qrf[kb] = ldsm4(sP + off);
    }
    __syncthreads();   // all Q fragments extracted before staging areas reused

    const int njt = (i0 >> 6) + 2;

    // tile loader: K,V into buf (jt&1); rr rows (full 192 on first, else 64 new)
    auto load_tile = [&](int jt, bool full_rr) {
        const int j0 = jt * 64;
        const int l0 = Sq - 128 + j0 - i0;
        const uint32_t kb = sKb + (uint32_t)(jt & 1) * 9216u;
        const uint32_t vb = sVb + (uint32_t)(jt & 1) * 9216u;
        for (int e = tid; e < 64 * 8; e += 256) {
            int row = e >> 3, sg = e & 7;
            cp16(kb + (uint32_t)(row * FLH_STB + sg * 16),
                 &kp[kvbase + (long)(j0 + row) * Dm + sg * 8]);
            cp16(vb + (uint32_t)(row * FLH_STB + sg * 16),
                 &vp[kvbase + (long)(j0 + row) * Dm + sg * 8]);
        }
        int rlo = full_rr ? 0 : 128;
        for (int e = tid + rlo * 8; e < 192 * 8; e += 256) {
            int row = e >> 3, sg = e & 7;
            int l = l0 + row;
            int slot = l & 255;
            int lr = l > Sq - 1 ? Sq - 1 : l;
            cp16(sR + (uint32_t)(slot * FLH_STB + sg * 16),
                 &rp[kvbase + (long)lr * Dm + sg * 8]);
        }
    };

    float m0v = -1e30f, m1v = -1e30f, l0v = 0.f, l1v = 0.f;
    float o_[8][4];
    #pragma unroll
    for (int i = 0; i < 8; i++)
        #pragma unroll
        for (int j = 0; j < 4; j++) o_[i][j] = 0.f;

    load_tile(0, true); CP_COMMIT();

    for (int jt = 0; jt < njt; jt++) {
        const int j0 = jt * 64;
        const int l0 = Sq - 128 + j0 - i0;
        const uint32_t sK = sKb + (uint32_t)(jt & 1) * 9216u;
        const uint32_t sV = sVb + (uint32_t)(jt & 1) * 9216u;

        CP_WAIT_ALL();       // tile jt's loads complete
        __syncthreads();     // visible to all; prev tile's reads done
        if (jt + 1 < njt) { load_tile(jt + 1, false); CP_COMMIT(); }

        // ---- E band MMA: unconditional padded stores ----
        {
            int dlo = 105 - r0w; if (dlo < 0) dlo = 0; dlo &= ~7;
            int dhi = (190 - r0w) & ~7;
            for (int d0 = dlo; d0 <= dhi; d0 += 16) {
                bool has2 = (d0 + 8 <= dhi);
                float e0[4] = {0.f,0.f,0.f,0.f}, e1[4] = {0.f,0.f,0.f,0.f};
                int lb = l0 + d0 + (grp & 1) * 8;
                int slotb = lb & 255;
                #pragma unroll
                for (int kb = 0; kb < 4; kb++) {
                    uint4 bf = ldsm4(sR + (uint32_t)((slotb + rw) * FLH_STB)
                                     + kb * 32 + acol);
                    mma_f16(e0, qrf[kb], bf.x, bf.z);
                    if (has2) mma_f16(e1, qrf[kb], bf.y, bf.w);
                }
                int ii0 = r0w + r, ii1 = ii0 + 8;
                int d = d0 + 2 * c;
                int ja = d - 127 + ii0 + FLH_PBASE;
                int jb = d - 127 + ii1 + FLH_PBASE;
                Ph[ii0 * FLH_PST + ja    ] = __float2half_rn(e0[0]);
                Ph[ii0 * FLH_PST + ja + 1] = __float2half_rn(e0[1]);
                Ph[ii1 * FLH_PST + jb    ] = __float2half_rn(e0[2]);
                Ph[ii1 * FLH_PST + jb + 1] = __float2half_rn(e0[3]);
                if (has2) {
                    Ph[ii0 * FLH_PST + ja + 8] = __float2half_rn(e1[0]);
                    Ph[ii0 * FLH_PST + ja + 9] = __float2half_rn(e1[1]);
                    Ph[ii1 * FLH_PST + jb + 8] = __float2half_rn(e1[2]);
                    Ph[ii1 * FLH_PST + jb + 9] = __float2half_rn(e1[3]);
                }
            }
        }
        __syncwarp();

        // ---- ac MMA (fp16) ----
        float s_[8][4];
        #pragma unroll
        for (int i = 0; i < 8; i++)
            #pragma unroll
            for (int j = 0; j < 4; j++) s_[i][j] = 0.f;
        #pragma unroll
        for (int kb = 0; kb < 4; kb++) {
            #pragma unroll
            for (int nb = 0; nb < 4; nb++) {
                uint4 bq = ldsm4(sK + (uint32_t)((nb * 16 + rsel) * FLH_STB)
                                 + kb * 32 + acol);
                mma_f16(s_[2 * nb],     qwf[kb], bq.x, bq.z);
                mma_f16(s_[2 * nb + 1], qwf[kb], bq.y, bq.w);
            }
        }

        // ---- S = ac + E (pre-scaled), mask, online softmax ----
        const int gi0 = i0 + r0w + r, gi1 = gi0 + 8;
        float mx0 = -1e30f, mx1 = -1e30f;
        #pragma unroll
        for (int nt = 0; nt < 8; nt++) {
            int jj = nt * 8 + 2 * c, jg = j0 + jj;
            float e00 = __half2float(Ph[(r0w + r) * FLH_PST + FLH_PBASE + jj]);
            float e01 = __half2float(Ph[(r0w + r) * FLH_PST + FLH_PBASE + jj + 1]);
            float e10 = __half2float(Ph[(r0w + r + 8) * FLH_PST + FLH_PBASE + jj]);
            float e11 = __half2float(Ph[(r0w + r + 8) * FLH_PST + FLH_PBASE + jj + 1]);
            s_[nt][0] = (jg     <= gi0) ? (s_[nt][0] + e00) : -1e30f;
            s_[nt][1] = (jg + 1 <= gi0) ? (s_[nt][1] + e01) : -1e30f;
            s_[nt][2] = (jg     <= gi1) ? (s_[nt][2] + e10) : -1e30f;
            s_[nt][3] = (jg + 1 <= gi1) ? (s_[nt][3] + e11) : -1e30f;
            mx0 = fmaxf(mx0, fmaxf(s_[nt][0], s_[nt][1]));
            mx1 = fmaxf(mx1, fmaxf(s_[nt][2], s_[nt][3]));
        }
        mx0 = fmaxf(mx0, __shfl_xor_sync(0xffffffffu, mx0, 1));
        mx0 = fmaxf(mx0, __shfl_xor_sync(0xffffffffu, mx0, 2));
        mx1 = fmaxf(mx1, __shfl_xor_sync(0xffffffffu, mx1, 1));
        mx1 = fmaxf(mx1, __shfl_xor_sync(0xffffffffu, mx1, 2));
        float mn0 = fmaxf(m0v, mx0), mn1 = fmaxf(m1v, mx1);
        float a0 = __expf(m0v - mn0), a1 = __expf(m1v - mn1);
        float sum0 = 0.f, sum1 = 0.f;
        #pragma unroll
        for (int nt = 0; nt < 8; nt++) {
            int jj = nt * 8 + 2 * c;
            float p00 = __expf(s_[nt][0] - mn0), p01 = __expf(s_[nt][1] - mn0);
            float p10 = __expf(s_[nt][2] - mn1), p11 = __expf(s_[nt][3] - mn1);
            sum0 += p00 + p01; sum1 += p10 + p11;
            *(__half2*)&Ph[(r0w + r) * FLH_PST + FLH_PBASE + jj]     = __floats2half2_rn(p00, p01);
            *(__half2*)&Ph[(r0w + r + 8) * FLH_PST + FLH_PBASE + jj] = __floats2half2_rn(p10, p11);
        }
        sum0 += __shfl_xor_sync(0xffffffffu, sum0, 1);
        sum0 += __shfl_xor_sync(0xffffffffu, sum0, 2);
        sum1 += __shfl_xor_sync(0xffffffffu, sum1, 1);
        sum1 += __shfl_xor_sync(0xffffffffu, sum1, 2);
        l0v = l0v * a0 + sum0; l1v = l1v * a1 + sum1;
        m0v = mn0; m1v = mn1;
        #pragma unroll
        for (int dt = 0; dt < 8; dt++) {
            o_[dt][0] *= a0; o_[dt][1] *= a0;
            o_[dt][2] *= a1; o_[dt][3] *= a1;
        }
        __syncwarp();

        // ---- PV: O += P @ V (fp16); V^T fragments via ldmatrix.trans ----
        #pragma unroll
        for (int kb = 0; kb < 4; kb++) {
            uint4 af = ldsm4(sP + (uint32_t)((r0w + rsel) * FLH_PST * 2)
                             + FLH_PBASE * 2 + kb * 32 + acol);
            #pragma unroll
            for (int nb = 0; nb < 4; nb++) {
                uint4 bq = ldsm4t(sV + (uint32_t)((kb * 16 + (grp & 1) * 8 + rw) * FLH_STB)
                                  + nb * 32 + (grp >> 1) * 16);
                mma_f16(o_[2 * nb],     af, bq.x, bq.y);
                mma_f16(o_[2 * nb + 1], af, bq.z, bq.w);
            }
        }
    }

    // ---- epilogue: O / l, fp16 (feeds Wo hgemm) ----
    float i0v = 1.f / l0v, i1v = 1.f / l1v;
    long ob0 = ((long)(b * Sq + i0 + r0w + r)) * Dm + h * 64;
    long ob1 = ob0 + 8L * Dm;
    #pragma unroll
    for (int dt = 0; dt < 8; dt++) {
        int d = dt * 8 + 2 * c;
        *(__half2*)&avph[ob0 + d] = __floats2half2_rn(o_[dt][0] * i0v, o_[dt][1] * i0v);
        *(__half2*)&avph[ob1 + d] = __floats2half2_rn(o_[dt][2] * i1v, o_[dt][3] * i1v);
    }
}

// ---------------- reductions / LN --------------------------------------------
__device__ __forceinline__ float warpSum(float v) {
    #pragma unroll
    for (int o = 16; o > 0; o >>= 1) v += __shfl_xor_sync(0xffffffffu, v, o);
    return v;
}
__device__ float blockSum(float v) {
    __shared__ float red[8];
    __syncthreads();
    int lane = threadIdx.x & 31, wid = threadIdx.x >> 5;
    v = warpSum(v);
    if (lane == 0) red[wid] = v;
    __syncthreads();
    if (wid == 0) {
        float t = (lane < 8) ? red[lane] : 0.f;
        t = warpSum(t);
        if (lane == 0) red[0] = t;
    }
    __syncthreads();
    return red[0];
}

// Vectorized LN: one float4 per thread (Dm = 256 threads * 4), row in regs.
__global__ void ln_kernel(const float4* __restrict__ a, const float4* __restrict__ b,
                          const float4* __restrict__ gam, const float4* __restrict__ bet,
                          float4* __restrict__ out, __half* __restrict__ out_h)
{
    const long row = blockIdx.x;
    const int tid = threadIdx.x;
    const long idx = row * 256 + tid;

    float4 va = a[idx], vb = b[idx];
    float4 xv = make_float4(va.x + vb.x, va.y + vb.y, va.z + vb.z, va.w + vb.w);

    float mu = blockSum(xv.x + xv.y + xv.z + xv.w) * (1.f / Dm);
    float dx = xv.x - mu, dy = xv.y - mu, dz = xv.z - mu, dw = xv.w - mu;
    float var = blockSum(dx * dx + dy * dy + dz * dz + dw * dw) * (1.f / Dm);
    float inv = rsqrtf(var + EPS);

    float4 g = gam[tid], be = bet[tid];
    float4 y = make_float4(dx * inv * g.x + be.x, dy * inv * g.y + be.y,
                           dz * inv * g.z + be.z, dw * inv * g.w + be.w);
    out[idx] = y;
    if (out_h) {
        *(__half2*)&out_h[4 * idx]     = __floats2half2_rn(y.x, y.y);
        *(__half2*)&out_h[4 * idx + 2] = __floats2half2_rn(y.z, y.w);
    }
}

// ---------------- launch ----------------------------------------------------
extern "C" void kernel_launch(void* const* d_in, const int* in_sizes, int n_in,
                              void* d_out, int out_size)
{
    const float* w      = (const float*)d_in[0];
    const float* r      = (const float*)d_in[1];
    const float* w_bias = (const float*)d_in[2];
    const float* r_bias = (const float*)d_in[3];
    const float* b1     = (const float*)d_in[12];
    const float* b2     = (const float*)d_in[14];
    const float* ln1g   = (const float*)d_in[9];
    const float* ln1b   = (const float*)d_in[10];
    const float* ln2g   = (const float*)d_in[15];
    const float* ln2b   = (const float*)d_in[16];
    float* out = (float*)d_out;

    float *ao, *x, *f;
    __half *qwh, *qrh, *kh, *vh, *rrh, *avh, *xh, *hh, *wh, *rh;
    __half *Wqt, *Wkt, *Wvt, *Wrt, *Wot, *W1t, *W2t;
    cudaGetSymbolAddress((void**)&ao,  g_ao);
    cudaGetSymbolAddress((void**)&x,   g_x);
    cudaGetSymbolAddress((void**)&f,   g_f);
    cudaGetSymbolAddress((void**)&qwh, g_qwh);
    cudaGetSymbolAddress((void**)&qrh, g_qrh);
    cudaGetSymbolAddress((void**)&kh,  g_kh);
    cudaGetSymbolAddress((void**)&vh,  g_vh);
    cudaGetSymbolAddress((void**)&rrh, g_rrh);
    cudaGetSymbolAddress((void**)&avh, g_avh);
    cudaGetSymbolAddress((void**)&xh,  g_xh);
    cudaGetSymbolAddress((void**)&hh,  g_hh);
    cudaGetSymbolAddress((void**)&wh,  g_wh);
    cudaGetSymbolAddress((void**)&rh,  g_rh);
    cudaGetSymbolAddress((void**)&Wqt, g_Wqt);
    cudaGetSymbolAddress((void**)&Wkt, g_Wkt);
    cudaGetSymbolAddress((void**)&Wvt, g_Wvt);
    cudaGetSymbolAddress((void**)&Wrt, g_Wrt);
    cudaGetSymbolAddress((void**)&Wot, g_Wot);
    cudaGetSymbolAddress((void**)&W1t, g_W1t);
    cudaGetSymbolAddress((void**)&W2t, g_W2t);

    const int M = Bq * Sq;

    // 0a) fp16 conversion of activations w, r
    roundh_kernel<<<dim3(512, 2), 256>>>((const float4*)w, wh,
                                         (const float4*)r, rh,
                                         Bq * Sq * Dm / 4);

    // 0b) transpose + fp16 of the 7 weights (flattened exact grid)
    {
        T7 t{};
        const float* ins[7] = { (const float*)d_in[4], (const float*)d_in[5],
                                (const float*)d_in[6], (const float*)d_in[7],
                                (const float*)d_in[8], (const float*)d_in[11],
                                (const float*)d_in[13] };
        __half* outs[7] = { Wqt, Wkt, Wvt, Wrt, Wot, W1t, W2t };
        for (int i = 0; i < 7; i++) { t.in[i] = ins[i]; t.out[i] = outs[i]; }
        txp_kernel<<<13312, 256>>>(t);
    }

    // 1) four projections -> fp16 outputs; q-biases fused (qw & qr dual,
    //    both pre-scaled by 1/8)
    {
        SelH p{};
        p.A[0] = wh;  p.A[1] = wh;  p.A[2] = wh;  p.A[3] = rh;
        p.B[0] = Wqt; p.B[1] = Wkt; p.B[2] = Wvt; p.B[3] = Wrt;
        p.Ch[0] = qwh; p.Ch[1] = kh; p.Ch[2] = vh; p.Ch[3] = rrh;
        p.bias[0]  = w_bias;
        p.Ch2[0]   = qrh;
        p.bias2[0] = r_bias;
        launch_hg<false, 2>(dim3(Dm / 128, M / 128, 4), p, Dm, Dm);
    }

    // 2) fused fp16 flash attention (2-stage tile pipeline)
    cudaFuncSetAttribute(flash_kernel,
                         cudaFuncAttributeMaxDynamicSharedMemorySize, FLH_TOT);
    flash_kernel<<<512, 256, FLH_TOT>>>(qwh, qrh, kh, rrh, vh, avh);

    // 3) attn_out = av @ Wo (fp32 out)
    {
        SelH p{};
        p.A[0] = avh; p.B[0] = Wot; p.C[0] = ao;
        launch_hg<false, 0>(dim3(Dm / 128, M / 128, 1), p, Dm, Dm);
    }

    // 4) x = LN(w + attn_out); xh = fp16(x)
    ln_kernel<<<M, 256>>>((const float4*)w, (const float4*)ao,
                          (const float4*)ln1g, (const float4*)ln1b,
                          (float4*)x, xh);

    // 5) FFN: hh = fp16(relu(x @ W1 + b1)); f = hh @ W2 + b2
    {
        SelH p{};
        p.A[0] = xh; p.B[0] = W1t; p.bias[0] = b1; p.Ch[0] = hh;
        launch_hg<true, 2>(dim3(DIf / 128, M / 128, 1), p, Dm, DIf);
    }
    {
        SelH p{};
        p.A[0] = hh; p.B[0] = W2t; p.bias[0] = b2; p.C[0] = f;
        launch_hg<false, 0>(dim3(Dm / 128, M / 128, 1), p, DIf, Dm);
    }

    // 6) out = LN(x + f)
    ln_kernel<<<M, 256>>>((const float4*)x, (const float4*)f,
                          (const float4*)ln2g, (const float4*)ln2b,
                          (float4*)out, nullptr);
}